// round 9
// baseline (speedup 1.0000x reference)
#include <cuda_runtime.h>
#include <cuda_fp16.h>
#include <math.h>
#include <stdint.h>

// ---------------- problem constants ----------------
static constexpr int B_   = 4;
static constexpr int NTOK = 1569;
static constexpr int C_   = 768;
static constexpr int H_   = 12;
static constexpr int D_   = 64;
static constexpr int F_   = 9;            // CLS + 8 temporal tokens
static constexpr int BN   = B_ * NTOK;    // 6276
static constexpr int C3   = 3 * C_;       // 2304
static constexpr int DFF  = 4 * C_;       // 3072
static constexpr int SPLIT = 8;           // temporal-attention key split
static constexpr int NSP  = NTOK - F_;    // 1560 spatial keys

// ---------------- scratch (device globals; no allocs) ----------------
__device__ __align__(16) float g_qkv[BN * C3];        // qkv projection (fp32)
__device__ __align__(16) float g_out[BN * C_];        // proj output ("new x", fp32)
__device__ __align__(16) __half g_h[BN * C_];         // LN out (single fp16)
__device__ __align__(16) __half g_at[BN * C_];        // attn out (single fp16)
__device__ __align__(16) __half g_m[BN * DFF];        // fc1 out (single fp16)
__device__ __align__(16) __half g_wq_hi[C3 * C_], g_wq_lo[C3 * C_];
__device__ __align__(16) __half g_wp_hi[C_ * C_], g_wp_lo[C_ * C_];
__device__ __align__(16) __half g_w1_hi[DFF * C_], g_w1_lo[DFF * C_];
__device__ __align__(16) __half g_w2_hi[C_ * DFF], g_w2_lo[C_ * DFF];
__device__ float g_part[B_ * H_ * F_ * SPLIT * 66];   // split-softmax partials

// ---------------- helpers ----------------
__device__ __forceinline__ uint32_t smem_u32(const void* p) {
    uint32_t a;
    asm("{ .reg .u64 t; cvta.to.shared.u64 t, %1; cvt.u32.u64 %0, t; }" : "=r"(a) : "l"(p));
    return a;
}
__device__ __forceinline__ void cp16(uint32_t dst, const void* src, int sz) {
    asm volatile("cp.async.cg.shared.global [%0], [%1], 16, %2;" :: "r"(dst), "l"(src), "r"(sz) : "memory");
}
__device__ __forceinline__ void cp_commit() { asm volatile("cp.async.commit_group;" ::: "memory"); }
template <int N>
__device__ __forceinline__ void cp_wait() { asm volatile("cp.async.wait_group %0;" :: "n"(N) : "memory"); }

__device__ __forceinline__ void ldm_x4(uint32_t* r, uint32_t addr) {
    asm volatile("ldmatrix.sync.aligned.m8n8.x4.shared.b16 {%0,%1,%2,%3}, [%4];"
                 : "=r"(r[0]), "=r"(r[1]), "=r"(r[2]), "=r"(r[3]) : "r"(addr));
}
__device__ __forceinline__ void mma_f16(float* d, const uint32_t* a, uint32_t b0, uint32_t b1) {
    asm volatile("mma.sync.aligned.m16n8k16.row.col.f32.f16.f16.f32 "
                 "{%0,%1,%2,%3}, {%4,%5,%6,%7}, {%8,%9}, {%0,%1,%2,%3};"
                 : "+f"(d[0]), "+f"(d[1]), "+f"(d[2]), "+f"(d[3])
                 : "r"(a[0]), "r"(a[1]), "r"(a[2]), "r"(a[3]), "r"(b0), "r"(b1));
}

__device__ __forceinline__ void split_f16(float v, __half& hi, __half& lo) {
    hi = __float2half_rn(v);
    lo = __float2half_rn(v - __half2float(hi));
}

// ---------------- weight split kernels (fp16 hi/lo) ----------------
template <int WID>
__global__ void __launch_bounds__(256) cvt_kernel(const float* __restrict__ w, int n) {
    __half* hi; __half* lo;
    if constexpr (WID == 0) { hi = g_wq_hi; lo = g_wq_lo; }
    else if constexpr (WID == 1) { hi = g_wp_hi; lo = g_wp_lo; }
    else if constexpr (WID == 2) { hi = g_w1_hi; lo = g_w1_lo; }
    else { hi = g_w2_hi; lo = g_w2_lo; }
    int i = blockIdx.x * 256 + threadIdx.x;
    if (i < n) { __half h, l; split_f16(w[i], h, l); hi[i] = h; lo[i] = l; }
}

// ---------------- LayerNorm -> fp16 into g_h ----------------
template <bool FROM_OUT>
__global__ void __launch_bounds__(256) ln_kernel(const float* __restrict__ ext_in,
                                                 const float* __restrict__ gam,
                                                 const float* __restrict__ bet) {
    const float* in = FROM_OUT ? g_out : ext_in;
    int row = blockIdx.x;
    const float* x = in + (size_t)row * C_;
    int tid = threadIdx.x;
    float v0 = x[tid], v1 = x[tid + 256], v2 = x[tid + 512];
    float s  = v0 + v1 + v2;
    float ss = v0 * v0 + v1 * v1 + v2 * v2;
#pragma unroll
    for (int off = 16; off; off >>= 1) {
        s  += __shfl_xor_sync(0xffffffffu, s, off);
        ss += __shfl_xor_sync(0xffffffffu, ss, off);
    }
    __shared__ float sm[8], sm2[8], stats[2];
    int warp = tid >> 5, lane = tid & 31;
    if (lane == 0) { sm[warp] = s; sm2[warp] = ss; }
    __syncthreads();
    if (tid == 0) {
        float S = 0.f, SS = 0.f;
#pragma unroll
        for (int w = 0; w < 8; w++) { S += sm[w]; SS += sm2[w]; }
        float mean = S * (1.0f / C_);
        float var  = SS * (1.0f / C_) - mean * mean;
        stats[0] = mean;
        stats[1] = rsqrtf(var + 1e-5f);
    }
    __syncthreads();
    float mean = stats[0], rstd = stats[1];
    size_t base = (size_t)row * C_;
#pragma unroll
    for (int t = 0; t < 3; t++) {
        int c = tid + t * 256;
        float v = t == 0 ? v0 : (t == 1 ? v1 : v2);
        float y = (v - mean) * rstd * gam[c] + bet[c];
        g_h[base + c] = __float2half_rn(y);
    }
}

// ---------------- HMMA GEMM: C[M,Nn] = A[M,K] @ W[Nn,K]^T ----------------
// 2-term fp16: A (single fp16) x (Whi + Wlo), fp32 accumulate.
// Warp tile 64M x 32N (2 M-warps x 4 N-warps) -> 32 LDSM per chunk (was 40).
static constexpr int STAGE_BYTES = 49152;   // A 16KB | Bhi 16KB | Blo 16KB, xor-swizzled
static constexpr int SMEM_DYN = 2 * STAGE_BYTES;   // 96 KB -> 2 blocks/SM

template <int CFG>
__global__ void __launch_bounds__(256, 2)
gemm_mma(const float* __restrict__ bias, float* __restrict__ ext_out) {
    constexpr int Nn = (CFG == 0) ? C3 : (CFG == 2) ? DFF : C_;
    constexpr int K  = (CFG == 3) ? DFF : C_;
    constexpr int NC = K / 64;

    const __half* A   = (CFG == 0 || CFG == 2) ? g_h : (CFG == 1) ? g_at : g_m;
    const __half* Whi = (CFG == 0) ? g_wq_hi : (CFG == 1) ? g_wp_hi : (CFG == 2) ? g_w1_hi : g_w2_hi;
    const __half* Wlo = (CFG == 0) ? g_wq_lo : (CFG == 1) ? g_wp_lo : (CFG == 2) ? g_w1_lo : g_w2_lo;

    extern __shared__ char smraw[];
    uint32_t sbu = smem_u32(smraw);

    int tid = threadIdx.x, lane = tid & 31, wid = tid >> 5;
    int n0 = blockIdx.x * 128, m0 = blockIdx.y * 128;
    int wm0 = (wid >> 2) * 64, wn0 = (wid & 3) * 32;

    // issue one 64-wide K chunk into stage s
    auto issue = [&](int c, int s) {
        int k0 = c * 64;
        uint32_t sb = sbu + (uint32_t)s * STAGE_BYTES;
#pragma unroll
        for (int it = 0; it < 4; it++) {
            int idx = tid + it * 256;          // 0..1023
            int row = idx >> 3, unit = idx & 7;
            uint32_t soff = (uint32_t)row * 128u + (uint32_t)((unit ^ (row & 7)) << 4);
            int grA = m0 + row;
            int szA = (grA < BN) ? 16 : 0;
            cp16(sb + soff, A + (size_t)grA * K + k0 + unit * 8, szA);
            cp16(sb + 16384 + soff, Whi + (size_t)(n0 + row) * K + k0 + unit * 8, 16);
            cp16(sb + 32768 + soff, Wlo + (size_t)(n0 + row) * K + k0 + unit * 8, 16);
        }
        cp_commit();
    };

    float d[4][4][4];
#pragma unroll
    for (int i = 0; i < 4; i++)
#pragma unroll
        for (int j = 0; j < 4; j++)
#pragma unroll
            for (int q = 0; q < 4; q++) d[i][j][q] = 0.f;

    issue(0, 0);
    for (int c = 0; c < NC; c++) {
        if (c + 1 < NC) { issue(c + 1, (c + 1) & 1); cp_wait<1>(); }
        else            { cp_wait<0>(); }
        __syncthreads();
        uint32_t sb = sbu + (uint32_t)(c & 1) * STAGE_BYTES;
#pragma unroll
        for (int kk = 0; kk < 4; kk++) {
            uint32_t a[4][4];
#pragma unroll
            for (int mt = 0; mt < 4; mt++) {
                int row = wm0 + mt * 16 + (lane & 15);
                int unit = kk * 2 + (lane >> 4);
                uint32_t off = (uint32_t)row * 128u + (uint32_t)((unit ^ (row & 7)) << 4);
                ldm_x4(a[mt], sb + off);
            }
#pragma unroll
            for (int ng = 0; ng < 2; ng++) {
                int row = wn0 + ng * 16 + (lane & 15);
                int unit = kk * 2 + (lane >> 4);
                uint32_t off = (uint32_t)row * 128u + (uint32_t)((unit ^ (row & 7)) << 4);
                uint32_t bh4[4], bl4[4];
                ldm_x4(bh4, sb + 16384 + off);
                ldm_x4(bl4, sb + 32768 + off);
#pragma unroll
                for (int mt = 0; mt < 4; mt++)
#pragma unroll
                    for (int hf = 0; hf < 2; hf++) {
                        int nt = ng * 2 + hf;
                        mma_f16(d[mt][nt], a[mt], bh4[hf], bh4[hf + 2]);
                        mma_f16(d[mt][nt], a[mt], bl4[hf], bl4[hf + 2]);
                    }
            }
        }
        __syncthreads();
    }

    // epilogue: direct register -> global
#pragma unroll
    for (int mt = 0; mt < 4; mt++) {
#pragma unroll
        for (int half = 0; half < 2; half++) {
            int grow = m0 + wm0 + mt * 16 + (lane >> 2) + half * 8;
            if (grow >= BN) continue;
#pragma unroll
            for (int nt = 0; nt < 4; nt++) {
                int gc = n0 + wn0 + nt * 8 + (lane & 3) * 2;
                float v0 = d[mt][nt][half * 2 + 0];
                float v1 = d[mt][nt][half * 2 + 1];
                if constexpr (CFG == 0) {
                    *(float2*)&g_qkv[(size_t)grow * Nn + gc] = make_float2(v0, v1);
                } else if constexpr (CFG == 1) {
                    v0 += bias[gc]; v1 += bias[gc + 1];
                    *(float2*)&g_out[(size_t)grow * Nn + gc] = make_float2(v0, v1);
                } else if constexpr (CFG == 2) {
                    v0 += bias[gc]; v1 += bias[gc + 1];
                    v0 = 0.5f * v0 * (1.0f + erff(v0 * 0.70710678f));
                    v1 = 0.5f * v1 * (1.0f + erff(v1 * 0.70710678f));
                    size_t o = (size_t)grow * Nn + gc;
                    g_m[o]     = __float2half_rn(v0);
                    g_m[o + 1] = __float2half_rn(v1);
                } else {
                    size_t o = (size_t)grow * Nn + gc;
                    v0 += bias[gc]     + g_out[o];
                    v1 += bias[gc + 1] + g_out[o + 1];
                    *(float2*)&ext_out[o] = make_float2(v0, v1);
                }
            }
        }
    }
}

// ---------------- attention, spatial rows (i >= F): 9 keys each ----------------
__global__ void __launch_bounds__(256) attn_spatial() {
    const float* qkv = g_qkv;
    const int CH = NSP / 8;             // 195
    int bid   = blockIdx.x;
    int chunk = bid % CH;
    int bh    = bid / CH;
    int h     = bh % H_;
    int b     = bh / H_;

    __shared__ float ks[F_][D_], vs[F_][D_];
    int tid = threadIdx.x;
    for (int idx = tid; idx < F_ * D_; idx += 256) {
        int j = idx / D_, dd = idx % D_;
        const float* base = qkv + ((size_t)(b * NTOK + j)) * C3 + h * D_;
        ks[j][dd] = base[C_ + dd];
        vs[j][dd] = base[2 * C_ + dd];
    }
    __syncthreads();

    int warp = tid >> 5, lane = tid & 31;
    int i = F_ + chunk * 8 + warp;
    const float* q = qkv + ((size_t)(b * NTOK + i)) * C3 + h * D_;
    float q0 = q[lane], q1 = q[lane + 32];

    float lg[F_];
#pragma unroll
    for (int j = 0; j < F_; j++) {
        float p = q0 * ks[j][lane] + q1 * ks[j][lane + 32];
#pragma unroll
        for (int off = 16; off; off >>= 1) p += __shfl_xor_sync(0xffffffffu, p, off);
        lg[j] = p * 0.125f;
    }
    float m = lg[0];
#pragma unroll
    for (int j = 1; j < F_; j++) m = fmaxf(m, lg[j]);
    float s = 0.f, a0 = 0.f, a1 = 0.f;
#pragma unroll
    for (int j = 0; j < F_; j++) {
        float w = expf(lg[j] - m);
        s += w;
        a0 += w * vs[j][lane];
        a1 += w * vs[j][lane + 32];
    }
    float inv = 1.0f / s;
    size_t off0 = ((size_t)(b * NTOK + i)) * C_ + h * D_;
    g_at[off0 + lane]      = __float2half_rn(a0 * inv);
    g_at[off0 + lane + 32] = __float2half_rn(a1 * inv);
}

// ---------------- temporal rows: merged split-softmax partials ----------------
// one block per (b,h,sp); handles ALL 9 temporal rows; K/V read once.
__global__ void __launch_bounds__(256) attn_tpart() {
    const float* qkv = g_qkv;
    int bid = blockIdx.x;               // 0 .. B*H*SPLIT-1
    int sp = bid % SPLIT;
    int bh = bid / SPLIT;
    int h  = bh % H_;
    int b  = bh / H_;

    __shared__ float qsh[F_][D_];
    __shared__ float wm[8][F_], ws[8][F_];
    __shared__ float accs[8][F_][D_];
    __shared__ float wlog[8][25][F_];

    int tid = threadIdx.x, w = tid >> 5, lane = tid & 31;
    for (int idx = tid; idx < F_ * D_; idx += 256) {
        int i = idx / D_, dd = idx % D_;
        qsh[i][dd] = qkv[((size_t)(b * NTOK + i)) * C3 + h * D_ + dd];
    }
    __syncthreads();
    float q0[F_], q1[F_];
#pragma unroll
    for (int i = 0; i < F_; i++) { q0[i] = qsh[i][lane]; q1[i] = qsh[i][lane + 32]; }

    int g = sp * 8 + w;                 // global warp 0..63 strides the 1560 keys

    float m[F_], s[F_];
#pragma unroll
    for (int i = 0; i < F_; i++) { m[i] = -1e30f; s[i] = 0.f; }

    // pass 1: logits for all 9 rows per key; cache; online max/sum
    int it = 0;
    for (int tt = g; tt < NSP; tt += 64, it++) {
        const float* kp = qkv + ((size_t)(b * NTOK + F_ + tt)) * C3 + C_ + h * D_;
        float k0 = kp[lane], k1 = kp[lane + 32];
#pragma unroll
        for (int i = 0; i < F_; i++) {
            float p = q0[i] * k0 + q1[i] * k1;
#pragma unroll
            for (int off = 16; off; off >>= 1) p += __shfl_xor_sync(0xffffffffu, p, off);
            float lg = p * 0.125f;
            if (lane == 0) wlog[w][it][i] = lg;
            if (lg > m[i]) { s[i] *= expf(m[i] - lg); m[i] = lg; }
            s[i] += expf(lg - m[i]);
        }
    }
    // CLS key (j=0) contributes to row i=0 only; handled by global warp 0
    float clslog = 0.f;
    if (g == 0) {
        const float* kp = qkv + ((size_t)(b * NTOK + 0)) * C3 + C_ + h * D_;
        float p = q0[0] * kp[lane] + q1[0] * kp[lane + 32];
#pragma unroll
        for (int off = 16; off; off >>= 1) p += __shfl_xor_sync(0xffffffffu, p, off);
        clslog = p * 0.125f;
        if (clslog > m[0]) { s[0] *= expf(m[0] - clslog); m[0] = clslog; }
        s[0] += expf(clslog - m[0]);
    }
    if (lane == 0) {
#pragma unroll
        for (int i = 0; i < F_; i++) { wm[w][i] = m[i]; ws[w][i] = s[i]; }
    }
    __syncthreads();

    // block-level (per split) max/sum, computed redundantly by all threads
    float Mb[F_], Sb[F_];
#pragma unroll
    for (int i = 0; i < F_; i++) {
        float M = wm[0][i];
#pragma unroll
        for (int k = 1; k < 8; k++) M = fmaxf(M, wm[k][i]);
        float S = 0.f;
#pragma unroll
        for (int k = 0; k < 8; k++) S += ws[k][i] * expf(wm[k][i] - M);
        Mb[i] = M; Sb[i] = S;
    }

    // pass 2: V accumulation with cached logits
    float a0[F_], a1[F_];
#pragma unroll
    for (int i = 0; i < F_; i++) { a0[i] = 0.f; a1[i] = 0.f; }
    it = 0;
    for (int tt = g; tt < NSP; tt += 64, it++) {
        const float* vp = qkv + ((size_t)(b * NTOK + F_ + tt)) * C3 + 2 * C_ + h * D_;
        float v0 = vp[lane], v1 = vp[lane + 32];
#pragma unroll
        for (int i = 0; i < F_; i++) {
            float w8 = expf(wlog[w][it][i] - Mb[i]);
            a0[i] += w8 * v0;
            a1[i] += w8 * v1;
        }
    }
    if (g == 0) {
        const float* vp = qkv + ((size_t)(b * NTOK + 0)) * C3 + 2 * C_ + h * D_;
        float w8 = expf(clslog - Mb[0]);
        a0[0] += w8 * vp[lane];
        a1[0] += w8 * vp[lane + 32];
    }
#pragma unroll
    for (int i = 0; i < F_; i++) {
        accs[w][i][lane]      = a0[i];
        accs[w][i][lane + 32] = a1[i];
    }
    __syncthreads();

    for (int idx = tid; idx < F_ * D_; idx += 256) {
        int i = idx / D_, dd = idx % D_;
        float acc = 0.f;
#pragma unroll
        for (int k = 0; k < 8; k++) acc += accs[k][i][dd];
        float* pp = g_part + (size_t)(((bh * F_ + i) * SPLIT) + sp) * 66;
        pp[2 + dd] = acc;
        if (dd == 0) { pp[0] = Mb[i]; pp[1] = Sb[i]; }
    }
}

__global__ void __launch_bounds__(64) attn_tred() {
    int t = blockIdx.x;                 // 0 .. B*H*F-1  (t = bh*F + i)
    int i  = t % F_;
    int bh = t / F_;
    int h = bh % H_;
    int b = bh / H_;
    int d = threadIdx.x;

    float ms[SPLIT], ss[SPLIT];
    float M = -1e30f;
#pragma unroll
    for (int sp = 0; sp < SPLIT; sp++) {
        const float* pp = g_part + (size_t)(t * SPLIT + sp) * 66;
        ms[sp] = pp[0]; ss[sp] = pp[1];
        M = fmaxf(M, ms[sp]);
    }
    float S = 0.f, acc = 0.f;
#pragma unroll
    for (int sp = 0; sp < SPLIT; sp++) {
        float e = expf(ms[sp] - M);
        S += ss[sp] * e;
        acc += g_part[(size_t)(t * SPLIT + sp) * 66 + 2 + d] * e;
    }
    g_at[((size_t)(b * NTOK + i)) * C_ + h * D_ + d] = __float2half_rn(acc / S);
}

// ---------------- launch ----------------
extern "C" void kernel_launch(void* const* d_in, const int* in_sizes, int n_in,
                              void* d_out, int out_size) {
    const float* x     = (const float*)d_in[0];
    const float* ln_g  = (const float*)d_in[1];
    const float* ln_b  = (const float*)d_in[2];
    const float* qkvw  = (const float*)d_in[3];
    const float* projw = (const float*)d_in[4];
    const float* projb = (const float*)d_in[5];
    const float* fc1w  = (const float*)d_in[6];
    const float* fc1b  = (const float*)d_in[7];
    const float* fc2w  = (const float*)d_in[8];
    const float* fc2b  = (const float*)d_in[9];
    float* out = (float*)d_out;

    cudaFuncSetAttribute(gemm_mma<0>, cudaFuncAttributeMaxDynamicSharedMemorySize, SMEM_DYN);
    cudaFuncSetAttribute(gemm_mma<1>, cudaFuncAttributeMaxDynamicSharedMemorySize, SMEM_DYN);
    cudaFuncSetAttribute(gemm_mma<2>, cudaFuncAttributeMaxDynamicSharedMemorySize, SMEM_DYN);
    cudaFuncSetAttribute(gemm_mma<3>, cudaFuncAttributeMaxDynamicSharedMemorySize, SMEM_DYN);

    // weight splits (fp16 hi/lo)
    cvt_kernel<0><<<(C3 * C_ + 255) / 256, 256>>>(qkvw, C3 * C_);
    cvt_kernel<1><<<(C_ * C_ + 255) / 256, 256>>>(projw, C_ * C_);
    cvt_kernel<2><<<(DFF * C_ + 255) / 256, 256>>>(fc1w, DFF * C_);
    cvt_kernel<3><<<(C_ * DFF + 255) / 256, 256>>>(fc2w, C_ * DFF);

    // 1. g_h = fp16(LN(x))
    ln_kernel<false><<<BN, 256>>>(x, ln_g, ln_b);

    // 2. g_qkv = g_h @ qkv_w^T
    gemm_mma<0><<<dim3(C3 / 128, (BN + 127) / 128), 256, SMEM_DYN>>>(nullptr, nullptr);

    // 3. masked attention -> g_at (fp16)
    attn_spatial<<<B_ * H_ * (NSP / 8), 256>>>();
    attn_tpart<<<B_ * H_ * SPLIT, 256>>>();
    attn_tred<<<B_ * H_ * F_, 64>>>();

    // 4. g_out = g_at @ proj_w^T + proj_b
    gemm_mma<1><<<dim3(C_ / 128, (BN + 127) / 128), 256, SMEM_DYN>>>(projb, nullptr);

    // 5. g_h = fp16(LN(g_out))
    ln_kernel<true><<<BN, 256>>>(nullptr, ln_g, ln_b);

    // 6. g_m = fp16(GELU(g_h @ fc1_w^T + fc1_b))
    gemm_mma<2><<<dim3(DFF / 128, (BN + 127) / 128), 256, SMEM_DYN>>>(fc1b, nullptr);

    // 7. d_out = g_out + g_m @ fc2_w^T + fc2_b
    gemm_mma<3><<<dim3(C_ / 128, (BN + 127) / 128), 256, SMEM_DYN>>>(fc2b, out);
}

// round 10
// speedup vs baseline: 1.0884x; 1.0884x over previous
#include <cuda_runtime.h>
#include <cuda_fp16.h>
#include <math.h>
#include <stdint.h>

// ---------------- problem constants ----------------
static constexpr int B_   = 4;
static constexpr int NTOK = 1569;
static constexpr int C_   = 768;
static constexpr int H_   = 12;
static constexpr int D_   = 64;
static constexpr int F_   = 9;            // CLS + 8 temporal tokens
static constexpr int BN   = B_ * NTOK;    // 6276
static constexpr int C3   = 3 * C_;       // 2304
static constexpr int DFF  = 4 * C_;       // 3072
static constexpr int SPLIT = 8;           // temporal-attention key split
static constexpr int NSP  = NTOK - F_;    // 1560 spatial keys

// ---------------- scratch (device globals; no allocs) ----------------
__device__ __align__(16) float g_qkv[BN * C3];        // qkv projection (fp32)
__device__ __align__(16) float g_out[BN * C_];        // proj output ("new x", fp32)
__device__ __align__(16) __half g_h[BN * C_];         // LN out (single fp16)
__device__ __align__(16) __half g_at[BN * C_];        // attn out (single fp16)
__device__ __align__(16) __half g_m[BN * DFF];        // fc1 out (single fp16)
__device__ __align__(16) __half g_wq_hi[C3 * C_], g_wq_lo[C3 * C_];
__device__ __align__(16) __half g_wp_hi[C_ * C_], g_wp_lo[C_ * C_];
__device__ __align__(16) __half g_w1_hi[DFF * C_], g_w1_lo[DFF * C_];
__device__ __align__(16) __half g_w2_hi[C_ * DFF], g_w2_lo[C_ * DFF];
__device__ float g_part[B_ * H_ * F_ * SPLIT * 66];   // split-softmax partials

// ---------------- helpers ----------------
__device__ __forceinline__ uint32_t smem_u32(const void* p) {
    uint32_t a;
    asm("{ .reg .u64 t; cvta.to.shared.u64 t, %1; cvt.u32.u64 %0, t; }" : "=r"(a) : "l"(p));
    return a;
}
__device__ __forceinline__ void cp16(uint32_t dst, const void* src, int sz) {
    asm volatile("cp.async.cg.shared.global [%0], [%1], 16, %2;" :: "r"(dst), "l"(src), "r"(sz) : "memory");
}
__device__ __forceinline__ void cp_commit() { asm volatile("cp.async.commit_group;" ::: "memory"); }
template <int N>
__device__ __forceinline__ void cp_wait() { asm volatile("cp.async.wait_group %0;" :: "n"(N) : "memory"); }

__device__ __forceinline__ void ldm_x4(uint32_t* r, uint32_t addr) {
    asm volatile("ldmatrix.sync.aligned.m8n8.x4.shared.b16 {%0,%1,%2,%3}, [%4];"
                 : "=r"(r[0]), "=r"(r[1]), "=r"(r[2]), "=r"(r[3]) : "r"(addr));
}
__device__ __forceinline__ void mma_f16(float* d, const uint32_t* a, uint32_t b0, uint32_t b1) {
    asm volatile("mma.sync.aligned.m16n8k16.row.col.f32.f16.f16.f32 "
                 "{%0,%1,%2,%3}, {%4,%5,%6,%7}, {%8,%9}, {%0,%1,%2,%3};"
                 : "+f"(d[0]), "+f"(d[1]), "+f"(d[2]), "+f"(d[3])
                 : "r"(a[0]), "r"(a[1]), "r"(a[2]), "r"(a[3]), "r"(b0), "r"(b1));
}

__device__ __forceinline__ void split_f16(float v, __half& hi, __half& lo) {
    hi = __float2half_rn(v);
    lo = __float2half_rn(v - __half2float(hi));
}

// ---------------- fused, vectorized weight split ----------------
static constexpr int WSEG0 = C3 * C_;              // 1769472
static constexpr int WSEG1 = WSEG0 + C_ * C_;      // 2359296
static constexpr int WSEG2 = WSEG1 + DFF * C_;     // 4718592
static constexpr int WTOT  = WSEG2 + C_ * DFF;     // 7077888

__global__ void __launch_bounds__(256) cvt_all(const float* __restrict__ wq,
                                               const float* __restrict__ wp,
                                               const float* __restrict__ w1,
                                               const float* __restrict__ w2) {
    int i4 = (blockIdx.x * 256 + threadIdx.x) * 4;
    if (i4 >= WTOT) return;
    const float* src; __half* hi; __half* lo; int loc;
    if (i4 < WSEG0)      { src = wq; hi = g_wq_hi; lo = g_wq_lo; loc = i4; }
    else if (i4 < WSEG1) { src = wp; hi = g_wp_hi; lo = g_wp_lo; loc = i4 - WSEG0; }
    else if (i4 < WSEG2) { src = w1; hi = g_w1_hi; lo = g_w1_lo; loc = i4 - WSEG1; }
    else                 { src = w2; hi = g_w2_hi; lo = g_w2_lo; loc = i4 - WSEG2; }
    float4 v = *(const float4*)(src + loc);
    __half h0, l0, h1, l1, h2, l2, h3, l3;
    split_f16(v.x, h0, l0); split_f16(v.y, h1, l1);
    split_f16(v.z, h2, l2); split_f16(v.w, h3, l3);
    __half2* hp = (__half2*)(hi + loc);
    __half2* lp = (__half2*)(lo + loc);
    hp[0] = __halves2half2(h0, h1); hp[1] = __halves2half2(h2, h3);
    lp[0] = __halves2half2(l0, l1); lp[1] = __halves2half2(l2, l3);
}

// ---------------- output-init kernels (absorb bias / residual for split-K) ----------------
__global__ void __launch_bounds__(256) init_out1(const float* __restrict__ bias) {
    int idx = (blockIdx.x * 256 + threadIdx.x) * 4;
    if (idx < BN * C_) *(float4*)&g_out[idx] = *(const float4*)&bias[idx % C_];
}
__global__ void __launch_bounds__(256) init_out3(const float* __restrict__ bias,
                                                 float* __restrict__ out) {
    int idx = (blockIdx.x * 256 + threadIdx.x) * 4;
    if (idx < BN * C_) {
        float4 g = *(const float4*)&g_out[idx];
        float4 b = *(const float4*)&bias[idx % C_];
        *(float4*)&out[idx] = make_float4(g.x + b.x, g.y + b.y, g.z + b.z, g.w + b.w);
    }
}

// ---------------- LayerNorm -> fp16 into g_h ----------------
template <bool FROM_OUT>
__global__ void __launch_bounds__(256) ln_kernel(const float* __restrict__ ext_in,
                                                 const float* __restrict__ gam,
                                                 const float* __restrict__ bet) {
    const float* in = FROM_OUT ? g_out : ext_in;
    int row = blockIdx.x;
    const float* x = in + (size_t)row * C_;
    int tid = threadIdx.x;
    float v0 = x[tid], v1 = x[tid + 256], v2 = x[tid + 512];
    float s  = v0 + v1 + v2;
    float ss = v0 * v0 + v1 * v1 + v2 * v2;
#pragma unroll
    for (int off = 16; off; off >>= 1) {
        s  += __shfl_xor_sync(0xffffffffu, s, off);
        ss += __shfl_xor_sync(0xffffffffu, ss, off);
    }
    __shared__ float sm[8], sm2[8], stats[2];
    int warp = tid >> 5, lane = tid & 31;
    if (lane == 0) { sm[warp] = s; sm2[warp] = ss; }
    __syncthreads();
    if (tid == 0) {
        float S = 0.f, SS = 0.f;
#pragma unroll
        for (int w = 0; w < 8; w++) { S += sm[w]; SS += sm2[w]; }
        float mean = S * (1.0f / C_);
        float var  = SS * (1.0f / C_) - mean * mean;
        stats[0] = mean;
        stats[1] = rsqrtf(var + 1e-5f);
    }
    __syncthreads();
    float mean = stats[0], rstd = stats[1];
    size_t base = (size_t)row * C_;
#pragma unroll
    for (int t = 0; t < 3; t++) {
        int c = tid + t * 256;
        float v = t == 0 ? v0 : (t == 1 ? v1 : v2);
        float y = (v - mean) * rstd * gam[c] + bet[c];
        g_h[base + c] = __float2half_rn(y);
    }
}

// ---------------- HMMA GEMM: C[M,Nn] = A[M,K] @ W[Nn,K]^T ----------------
// 2-term fp16: A (single fp16) x (Whi + Wlo), fp32 accumulate. 32Mx64N warp tile (R7 best).
// CFG 0: qkv (store)        CFG 1: proj  (split-K=2, atomicAdd into bias-init g_out)
// CFG 2: fc1 (+bias,GELU)   CFG 3: fc2   (split-K=2, atomicAdd into init'd ext_out)
static constexpr int STAGE_BYTES = 49152;   // A 16KB | Bhi 16KB | Blo 16KB, xor-swizzled
static constexpr int SMEM_DYN = 2 * STAGE_BYTES;   // 96 KB -> 2 blocks/SM

template <int CFG>
__global__ void __launch_bounds__(256, 2)
gemm_mma(const float* __restrict__ bias, float* __restrict__ ext_out) {
    constexpr int Nn = (CFG == 0) ? C3 : (CFG == 2) ? DFF : C_;
    constexpr int K  = (CFG == 3) ? DFF : C_;
    constexpr bool SK = (CFG == 1 || CFG == 3);
    constexpr int NCH = (K / 64) / (SK ? 2 : 1);    // chunks handled by this block

    const __half* A   = (CFG == 0 || CFG == 2) ? g_h : (CFG == 1) ? g_at : g_m;
    const __half* Whi = (CFG == 0) ? g_wq_hi : (CFG == 1) ? g_wp_hi : (CFG == 2) ? g_w1_hi : g_w2_hi;
    const __half* Wlo = (CFG == 0) ? g_wq_lo : (CFG == 1) ? g_wp_lo : (CFG == 2) ? g_w1_lo : g_w2_lo;

    extern __shared__ char smraw[];
    uint32_t sbu = smem_u32(smraw);

    int tid = threadIdx.x, lane = tid & 31, wid = tid >> 5;
    int n0 = blockIdx.x * 128, m0 = blockIdx.y * 128;
    int c0 = SK ? (int)blockIdx.z * NCH : 0;
    int wm0 = (wid & 3) * 32, wn0 = (wid >> 2) * 64;

    // issue one 64-wide K chunk (global chunk index) into stage s
    auto issue = [&](int c, int s) {
        int k0 = c * 64;
        uint32_t sb = sbu + (uint32_t)s * STAGE_BYTES;
#pragma unroll
        for (int it = 0; it < 4; it++) {
            int idx = tid + it * 256;          // 0..1023
            int row = idx >> 3, unit = idx & 7;
            uint32_t soff = (uint32_t)row * 128u + (uint32_t)((unit ^ (row & 7)) << 4);
            int grA = m0 + row;
            int szA = (grA < BN) ? 16 : 0;
            cp16(sb + soff, A + (size_t)grA * K + k0 + unit * 8, szA);
            cp16(sb + 16384 + soff, Whi + (size_t)(n0 + row) * K + k0 + unit * 8, 16);
            cp16(sb + 32768 + soff, Wlo + (size_t)(n0 + row) * K + k0 + unit * 8, 16);
        }
        cp_commit();
    };

    float d[2][8][4];
#pragma unroll
    for (int i = 0; i < 2; i++)
#pragma unroll
        for (int j = 0; j < 8; j++)
#pragma unroll
            for (int q = 0; q < 4; q++) d[i][j][q] = 0.f;

    issue(c0, 0);
    for (int cc = 0; cc < NCH; cc++) {
        if (cc + 1 < NCH) { issue(c0 + cc + 1, (cc + 1) & 1); cp_wait<1>(); }
        else              { cp_wait<0>(); }
        __syncthreads();
        uint32_t sb = sbu + (uint32_t)(cc & 1) * STAGE_BYTES;
#pragma unroll
        for (int kk = 0; kk < 4; kk++) {
            uint32_t a[2][4];
#pragma unroll
            for (int mt = 0; mt < 2; mt++) {
                int row = wm0 + mt * 16 + (lane & 15);
                int unit = kk * 2 + (lane >> 4);
                uint32_t off = (uint32_t)row * 128u + (uint32_t)((unit ^ (row & 7)) << 4);
                ldm_x4(a[mt], sb + off);
            }
#pragma unroll
            for (int ng = 0; ng < 4; ng++) {
                int row = wn0 + ng * 16 + (lane & 15);
                int unit = kk * 2 + (lane >> 4);
                uint32_t off = (uint32_t)row * 128u + (uint32_t)((unit ^ (row & 7)) << 4);
                uint32_t bh4[4], bl4[4];
                ldm_x4(bh4, sb + 16384 + off);
                ldm_x4(bl4, sb + 32768 + off);
#pragma unroll
                for (int mt = 0; mt < 2; mt++)
#pragma unroll
                    for (int hf = 0; hf < 2; hf++) {
                        int nt = ng * 2 + hf;
                        mma_f16(d[mt][nt], a[mt], bh4[hf], bh4[hf + 2]);
                        mma_f16(d[mt][nt], a[mt], bl4[hf], bl4[hf + 2]);
                    }
            }
        }
        __syncthreads();
    }

    // epilogue
#pragma unroll
    for (int mt = 0; mt < 2; mt++) {
#pragma unroll
        for (int half = 0; half < 2; half++) {
            int grow = m0 + wm0 + mt * 16 + (lane >> 2) + half * 8;
            if (grow >= BN) continue;
#pragma unroll
            for (int nt = 0; nt < 8; nt++) {
                int gc = n0 + wn0 + nt * 8 + (lane & 3) * 2;
                float v0 = d[mt][nt][half * 2 + 0];
                float v1 = d[mt][nt][half * 2 + 1];
                size_t o = (size_t)grow * Nn + gc;
                if constexpr (CFG == 0) {
                    *(float2*)&g_qkv[o] = make_float2(v0, v1);
                } else if constexpr (CFG == 1) {
                    atomicAdd(&g_out[o], v0);
                    atomicAdd(&g_out[o + 1], v1);
                } else if constexpr (CFG == 2) {
                    v0 += bias[gc]; v1 += bias[gc + 1];
                    v0 = 0.5f * v0 * (1.0f + erff(v0 * 0.70710678f));
                    v1 = 0.5f * v1 * (1.0f + erff(v1 * 0.70710678f));
                    g_m[o]     = __float2half_rn(v0);
                    g_m[o + 1] = __float2half_rn(v1);
                } else {
                    atomicAdd(&ext_out[o], v0);
                    atomicAdd(&ext_out[o + 1], v1);
                }
            }
        }
    }
}

// ---------------- attention, spatial rows (i >= F): 9 keys each ----------------
__global__ void __launch_bounds__(256) attn_spatial() {
    const float* qkv = g_qkv;
    const int CH = NSP / 8;             // 195
    int bid   = blockIdx.x;
    int chunk = bid % CH;
    int bh    = bid / CH;
    int h     = bh % H_;
    int b     = bh / H_;

    __shared__ float ks[F_][D_], vs[F_][D_];
    int tid = threadIdx.x;
    for (int idx = tid; idx < F_ * D_; idx += 256) {
        int j = idx / D_, dd = idx % D_;
        const float* base = qkv + ((size_t)(b * NTOK + j)) * C3 + h * D_;
        ks[j][dd] = base[C_ + dd];
        vs[j][dd] = base[2 * C_ + dd];
    }
    __syncthreads();

    int warp = tid >> 5, lane = tid & 31;
    int i = F_ + chunk * 8 + warp;
    const float* q = qkv + ((size_t)(b * NTOK + i)) * C3 + h * D_;
    float q0 = q[lane], q1 = q[lane + 32];

    float lg[F_];
#pragma unroll
    for (int j = 0; j < F_; j++) {
        float p = q0 * ks[j][lane] + q1 * ks[j][lane + 32];
#pragma unroll
        for (int off = 16; off; off >>= 1) p += __shfl_xor_sync(0xffffffffu, p, off);
        lg[j] = p * 0.125f;
    }
    float m = lg[0];
#pragma unroll
    for (int j = 1; j < F_; j++) m = fmaxf(m, lg[j]);
    float s = 0.f, a0 = 0.f, a1 = 0.f;
#pragma unroll
    for (int j = 0; j < F_; j++) {
        float w = expf(lg[j] - m);
        s += w;
        a0 += w * vs[j][lane];
        a1 += w * vs[j][lane + 32];
    }
    float inv = 1.0f / s;
    size_t off0 = ((size_t)(b * NTOK + i)) * C_ + h * D_;
    g_at[off0 + lane]      = __float2half_rn(a0 * inv);
    g_at[off0 + lane + 32] = __float2half_rn(a1 * inv);
}

// ---------------- temporal rows: merged split-softmax partials ----------------
// one block per (b,h,sp); handles ALL 9 temporal rows; K/V read once.
__global__ void __launch_bounds__(256) attn_tpart() {
    const float* qkv = g_qkv;
    int bid = blockIdx.x;               // 0 .. B*H*SPLIT-1
    int sp = bid % SPLIT;
    int bh = bid / SPLIT;
    int h  = bh % H_;
    int b  = bh / H_;

    __shared__ float qsh[F_][D_];
    __shared__ float wm[8][F_], ws[8][F_];
    __shared__ float accs[8][F_][D_];
    __shared__ float wlog[8][25][F_];

    int tid = threadIdx.x, w = tid >> 5, lane = tid & 31;
    for (int idx = tid; idx < F_ * D_; idx += 256) {
        int i = idx / D_, dd = idx % D_;
        qsh[i][dd] = qkv[((size_t)(b * NTOK + i)) * C3 + h * D_ + dd];
    }
    __syncthreads();
    float q0[F_], q1[F_];
#pragma unroll
    for (int i = 0; i < F_; i++) { q0[i] = qsh[i][lane]; q1[i] = qsh[i][lane + 32]; }

    int g = sp * 8 + w;                 // global warp 0..63 strides the 1560 keys

    float m[F_], s[F_];
#pragma unroll
    for (int i = 0; i < F_; i++) { m[i] = -1e30f; s[i] = 0.f; }

    // pass 1: logits for all 9 rows per key; cache; online max/sum
    int it = 0;
    for (int tt = g; tt < NSP; tt += 64, it++) {
        const float* kp = qkv + ((size_t)(b * NTOK + F_ + tt)) * C3 + C_ + h * D_;
        float k0 = kp[lane], k1 = kp[lane + 32];
#pragma unroll
        for (int i = 0; i < F_; i++) {
            float p = q0[i] * k0 + q1[i] * k1;
#pragma unroll
            for (int off = 16; off; off >>= 1) p += __shfl_xor_sync(0xffffffffu, p, off);
            float lg = p * 0.125f;
            if (lane == 0) wlog[w][it][i] = lg;
            if (lg > m[i]) { s[i] *= expf(m[i] - lg); m[i] = lg; }
            s[i] += expf(lg - m[i]);
        }
    }
    // CLS key (j=0) contributes to row i=0 only; handled by global warp 0
    float clslog = 0.f;
    if (g == 0) {
        const float* kp = qkv + ((size_t)(b * NTOK + 0)) * C3 + C_ + h * D_;
        float p = q0[0] * kp[lane] + q1[0] * kp[lane + 32];
#pragma unroll
        for (int off = 16; off; off >>= 1) p += __shfl_xor_sync(0xffffffffu, p, off);
        clslog = p * 0.125f;
        if (clslog > m[0]) { s[0] *= expf(m[0] - clslog); m[0] = clslog; }
        s[0] += expf(clslog - m[0]);
    }
    if (lane == 0) {
#pragma unroll
        for (int i = 0; i < F_; i++) { wm[w][i] = m[i]; ws[w][i] = s[i]; }
    }
    __syncthreads();

    // block-level (per split) max/sum, computed redundantly by all threads
    float Mb[F_], Sb[F_];
#pragma unroll
    for (int i = 0; i < F_; i++) {
        float M = wm[0][i];
#pragma unroll
        for (int k = 1; k < 8; k++) M = fmaxf(M, wm[k][i]);
        float S = 0.f;
#pragma unroll
        for (int k = 0; k < 8; k++) S += ws[k][i] * expf(wm[k][i] - M);
        Mb[i] = M; Sb[i] = S;
    }

    // pass 2: V accumulation with cached logits
    float a0[F_], a1[F_];
#pragma unroll
    for (int i = 0; i < F_; i++) { a0[i] = 0.f; a1[i] = 0.f; }
    it = 0;
    for (int tt = g; tt < NSP; tt += 64, it++) {
        const float* vp = qkv + ((size_t)(b * NTOK + F_ + tt)) * C3 + 2 * C_ + h * D_;
        float v0 = vp[lane], v1 = vp[lane + 32];
#pragma unroll
        for (int i = 0; i < F_; i++) {
            float w8 = expf(wlog[w][it][i] - Mb[i]);
            a0[i] += w8 * v0;
            a1[i] += w8 * v1;
        }
    }
    if (g == 0) {
        const float* vp = qkv + ((size_t)(b * NTOK + 0)) * C3 + 2 * C_ + h * D_;
        float w8 = expf(clslog - Mb[0]);
        a0[0] += w8 * vp[lane];
        a1[0] += w8 * vp[lane + 32];
    }
#pragma unroll
    for (int i = 0; i < F_; i++) {
        accs[w][i][lane]      = a0[i];
        accs[w][i][lane + 32] = a1[i];
    }
    __syncthreads();

    for (int idx = tid; idx < F_ * D_; idx += 256) {
        int i = idx / D_, dd = idx % D_;
        float acc = 0.f;
#pragma unroll
        for (int k = 0; k < 8; k++) acc += accs[k][i][dd];
        float* pp = g_part + (size_t)(((bh * F_ + i) * SPLIT) + sp) * 66;
        pp[2 + dd] = acc;
        if (dd == 0) { pp[0] = Mb[i]; pp[1] = Sb[i]; }
    }
}

__global__ void __launch_bounds__(64) attn_tred() {
    int t = blockIdx.x;                 // 0 .. B*H*F-1  (t = bh*F + i)
    int i  = t % F_;
    int bh = t / F_;
    int h = bh % H_;
    int b = bh / H_;
    int d = threadIdx.x;

    float ms[SPLIT], ss[SPLIT];
    float M = -1e30f;
#pragma unroll
    for (int sp = 0; sp < SPLIT; sp++) {
        const float* pp = g_part + (size_t)(t * SPLIT + sp) * 66;
        ms[sp] = pp[0]; ss[sp] = pp[1];
        M = fmaxf(M, ms[sp]);
    }
    float S = 0.f, acc = 0.f;
#pragma unroll
    for (int sp = 0; sp < SPLIT; sp++) {
        float e = expf(ms[sp] - M);
        S += ss[sp] * e;
        acc += g_part[(size_t)(t * SPLIT + sp) * 66 + 2 + d] * e;
    }
    g_at[((size_t)(b * NTOK + i)) * C_ + h * D_ + d] = __float2half_rn(acc / S);
}

// ---------------- launch ----------------
extern "C" void kernel_launch(void* const* d_in, const int* in_sizes, int n_in,
                              void* d_out, int out_size) {
    const float* x     = (const float*)d_in[0];
    const float* ln_g  = (const float*)d_in[1];
    const float* ln_b  = (const float*)d_in[2];
    const float* qkvw  = (const float*)d_in[3];
    const float* projw = (const float*)d_in[4];
    const float* projb = (const float*)d_in[5];
    const float* fc1w  = (const float*)d_in[6];
    const float* fc1b  = (const float*)d_in[7];
    const float* fc2w  = (const float*)d_in[8];
    const float* fc2b  = (const float*)d_in[9];
    float* out = (float*)d_out;

    cudaFuncSetAttribute(gemm_mma<0>, cudaFuncAttributeMaxDynamicSharedMemorySize, SMEM_DYN);
    cudaFuncSetAttribute(gemm_mma<1>, cudaFuncAttributeMaxDynamicSharedMemorySize, SMEM_DYN);
    cudaFuncSetAttribute(gemm_mma<2>, cudaFuncAttributeMaxDynamicSharedMemorySize, SMEM_DYN);
    cudaFuncSetAttribute(gemm_mma<3>, cudaFuncAttributeMaxDynamicSharedMemorySize, SMEM_DYN);

    const int INIT_BLOCKS = (BN * C_ / 4 + 255) / 256;

    // fused weight split (fp16 hi/lo)
    cvt_all<<<(WTOT / 4 + 255) / 256, 256>>>(qkvw, projw, fc1w, fc2w);

    // 1. g_h = fp16(LN(x))
    ln_kernel<false><<<BN, 256>>>(x, ln_g, ln_b);

    // 2. g_qkv = g_h @ qkv_w^T
    gemm_mma<0><<<dim3(C3 / 128, (BN + 127) / 128), 256, SMEM_DYN>>>(nullptr, nullptr);

    // 3. masked attention -> g_at (fp16); also init g_out = proj_b
    attn_spatial<<<B_ * H_ * (NSP / 8), 256>>>();
    attn_tpart<<<B_ * H_ * SPLIT, 256>>>();
    init_out1<<<INIT_BLOCKS, 256>>>(projb);
    attn_tred<<<B_ * H_ * F_, 64>>>();

    // 4. g_out += g_at @ proj_w^T  (split-K=2, atomic)
    gemm_mma<1><<<dim3(C_ / 128, (BN + 127) / 128, 2), 256, SMEM_DYN>>>(nullptr, nullptr);

    // 5. g_h = fp16(LN(g_out))
    ln_kernel<true><<<BN, 256>>>(nullptr, ln_g, ln_b);

    // 6. g_m = fp16(GELU(g_h @ fc1_w^T + fc1_b))
    gemm_mma<2><<<dim3(DFF / 128, (BN + 127) / 128), 256, SMEM_DYN>>>(fc1b, nullptr);

    // 7. out = g_out + fc2_b; out += g_m @ fc2_w^T  (split-K=2, atomic)
    init_out3<<<INIT_BLOCKS, 256>>>(fc2b, out);
    gemm_mma<3><<<dim3(C_ / 128, (BN + 127) / 128, 2), 256, SMEM_DYN>>>(nullptr, out);
}

// round 11
// speedup vs baseline: 1.5886x; 1.4596x over previous
#include <cuda_runtime.h>
#include <cuda_fp16.h>
#include <math.h>
#include <stdint.h>

// ---------------- problem constants ----------------
static constexpr int B_   = 4;
static constexpr int NTOK = 1569;
static constexpr int C_   = 768;
static constexpr int H_   = 12;
static constexpr int D_   = 64;
static constexpr int F_   = 9;            // CLS + 8 temporal tokens
static constexpr int BN   = B_ * NTOK;    // 6276
static constexpr int C3   = 3 * C_;       // 2304
static constexpr int DFF  = 4 * C_;       // 3072
static constexpr int SPLIT = 8;           // temporal-attention key split
static constexpr int NSP  = NTOK - F_;    // 1560 spatial keys

// ---------------- scratch (device globals; no allocs) ----------------
__device__ __align__(16) float g_qkv[BN * C3];        // qkv projection (fp32)
__device__ __align__(16) float g_out[BN * C_];        // proj output ("new x", fp32)
__device__ __align__(16) __half g_h[BN * C_];         // LN out (fp16)
__device__ __align__(16) __half g_at[BN * C_];        // attn out (fp16)
__device__ __align__(16) __half g_m[BN * DFF];        // fc1 out (fp16)
__device__ __align__(16) __half g_wq[C3 * C_];
__device__ __align__(16) __half g_wp[C_ * C_];
__device__ __align__(16) __half g_w1[DFF * C_];
__device__ __align__(16) __half g_w2[C_ * DFF];
__device__ float g_part[B_ * H_ * F_ * SPLIT * 66];   // split-softmax partials

// ---------------- helpers ----------------
__device__ __forceinline__ uint32_t smem_u32(const void* p) {
    uint32_t a;
    asm("{ .reg .u64 t; cvta.to.shared.u64 t, %1; cvt.u32.u64 %0, t; }" : "=r"(a) : "l"(p));
    return a;
}
__device__ __forceinline__ void cp16(uint32_t dst, const void* src, int sz) {
    asm volatile("cp.async.cg.shared.global [%0], [%1], 16, %2;" :: "r"(dst), "l"(src), "r"(sz) : "memory");
}
__device__ __forceinline__ void cp_commit() { asm volatile("cp.async.commit_group;" ::: "memory"); }
template <int N>
__device__ __forceinline__ void cp_wait() { asm volatile("cp.async.wait_group %0;" :: "n"(N) : "memory"); }

__device__ __forceinline__ void ldm_x4(uint32_t* r, uint32_t addr) {
    asm volatile("ldmatrix.sync.aligned.m8n8.x4.shared.b16 {%0,%1,%2,%3}, [%4];"
                 : "=r"(r[0]), "=r"(r[1]), "=r"(r[2]), "=r"(r[3]) : "r"(addr));
}
__device__ __forceinline__ void mma_f16(float* d, const uint32_t* a, uint32_t b0, uint32_t b1) {
    asm volatile("mma.sync.aligned.m16n8k16.row.col.f32.f16.f16.f32 "
                 "{%0,%1,%2,%3}, {%4,%5,%6,%7}, {%8,%9}, {%0,%1,%2,%3};"
                 : "+f"(d[0]), "+f"(d[1]), "+f"(d[2]), "+f"(d[3])
                 : "r"(a[0]), "r"(a[1]), "r"(a[2]), "r"(a[3]), "r"(b0), "r"(b1));
}

// ---------------- fused, vectorized weight convert (fp32 -> fp16) ----------------
static constexpr int WSEG0 = C3 * C_;
static constexpr int WSEG1 = WSEG0 + C_ * C_;
static constexpr int WSEG2 = WSEG1 + DFF * C_;
static constexpr int WTOT  = WSEG2 + C_ * DFF;

__global__ void __launch_bounds__(256) cvt_all(const float* __restrict__ wq,
                                               const float* __restrict__ wp,
                                               const float* __restrict__ w1,
                                               const float* __restrict__ w2) {
    int i4 = (blockIdx.x * 256 + threadIdx.x) * 4;
    if (i4 >= WTOT) return;
    const float* src; __half* dst; int loc;
    if (i4 < WSEG0)      { src = wq; dst = g_wq; loc = i4; }
    else if (i4 < WSEG1) { src = wp; dst = g_wp; loc = i4 - WSEG0; }
    else if (i4 < WSEG2) { src = w1; dst = g_w1; loc = i4 - WSEG1; }
    else                 { src = w2; dst = g_w2; loc = i4 - WSEG2; }
    float4 v = *(const float4*)(src + loc);
    __half2* hp = (__half2*)(dst + loc);
    hp[0] = __halves2half2(__float2half_rn(v.x), __float2half_rn(v.y));
    hp[1] = __halves2half2(__float2half_rn(v.z), __float2half_rn(v.w));
}

// ---------------- output-init kernels (absorb bias / residual for split-K) ----------------
__global__ void __launch_bounds__(256) init_out1(const float* __restrict__ bias) {
    int idx = (blockIdx.x * 256 + threadIdx.x) * 4;
    if (idx < BN * C_) *(float4*)&g_out[idx] = *(const float4*)&bias[idx % C_];
}
__global__ void __launch_bounds__(256) init_out3(const float* __restrict__ bias,
                                                 float* __restrict__ out) {
    int idx = (blockIdx.x * 256 + threadIdx.x) * 4;
    if (idx < BN * C_) {
        float4 g = *(const float4*)&g_out[idx];
        float4 b = *(const float4*)&bias[idx % C_];
        *(float4*)&out[idx] = make_float4(g.x + b.x, g.y + b.y, g.z + b.z, g.w + b.w);
    }
}

// ---------------- LayerNorm -> fp16 into g_h ----------------
template <bool FROM_OUT>
__global__ void __launch_bounds__(256) ln_kernel(const float* __restrict__ ext_in,
                                                 const float* __restrict__ gam,
                                                 const float* __restrict__ bet) {
    const float* in = FROM_OUT ? g_out : ext_in;
    int row = blockIdx.x;
    const float* x = in + (size_t)row * C_;
    int tid = threadIdx.x;
    float v0 = x[tid], v1 = x[tid + 256], v2 = x[tid + 512];
    float s  = v0 + v1 + v2;
    float ss = v0 * v0 + v1 * v1 + v2 * v2;
#pragma unroll
    for (int off = 16; off; off >>= 1) {
        s  += __shfl_xor_sync(0xffffffffu, s, off);
        ss += __shfl_xor_sync(0xffffffffu, ss, off);
    }
    __shared__ float sm[8], sm2[8], stats[2];
    int warp = tid >> 5, lane = tid & 31;
    if (lane == 0) { sm[warp] = s; sm2[warp] = ss; }
    __syncthreads();
    if (tid == 0) {
        float S = 0.f, SS = 0.f;
#pragma unroll
        for (int w = 0; w < 8; w++) { S += sm[w]; SS += sm2[w]; }
        float mean = S * (1.0f / C_);
        float var  = SS * (1.0f / C_) - mean * mean;
        stats[0] = mean;
        stats[1] = rsqrtf(var + 1e-5f);
    }
    __syncthreads();
    float mean = stats[0], rstd = stats[1];
    size_t base = (size_t)row * C_;
#pragma unroll
    for (int t = 0; t < 3; t++) {
        int c = tid + t * 256;
        float v = t == 0 ? v0 : (t == 1 ? v1 : v2);
        float y = (v - mean) * rstd * gam[c] + bet[c];
        g_h[base + c] = __float2half_rn(y);
    }
}

// ---------------- HMMA GEMM: C[M,Nn] = A[M,K] @ W[Nn,K]^T (plain fp16 x fp16) ----------------
// CFG 0: qkv (store)        CFG 1: proj  (split-K=2, atomicAdd into bias-init g_out)
// CFG 2: fc1 (+bias,GELU)   CFG 3: fc2   (split-K=2, atomicAdd into init'd ext_out)
static constexpr int STAGE_BYTES = 32768;   // A 16KB | W 16KB, xor-swizzled
static constexpr int SMEM_DYN = 2 * STAGE_BYTES;   // 64 KB

template <int CFG>
__global__ void __launch_bounds__(256, 2)
gemm_mma(const float* __restrict__ bias, float* __restrict__ ext_out) {
    constexpr int Nn = (CFG == 0) ? C3 : (CFG == 2) ? DFF : C_;
    constexpr int K  = (CFG == 3) ? DFF : C_;
    constexpr bool SK = (CFG == 1 || CFG == 3);
    constexpr int NCH = (K / 64) / (SK ? 2 : 1);

    const __half* A = (CFG == 0 || CFG == 2) ? g_h : (CFG == 1) ? g_at : g_m;
    const __half* W = (CFG == 0) ? g_wq : (CFG == 1) ? g_wp : (CFG == 2) ? g_w1 : g_w2;

    extern __shared__ char smraw[];
    uint32_t sbu = smem_u32(smraw);

    int tid = threadIdx.x, lane = tid & 31, wid = tid >> 5;
    int n0 = blockIdx.x * 128, m0 = blockIdx.y * 128;
    int c0 = SK ? (int)blockIdx.z * NCH : 0;
    int wm0 = (wid & 3) * 32, wn0 = (wid >> 2) * 64;

    // issue one 64-wide K chunk (global chunk index) into stage s
    auto issue = [&](int c, int s) {
        int k0 = c * 64;
        uint32_t sb = sbu + (uint32_t)s * STAGE_BYTES;
#pragma unroll
        for (int it = 0; it < 4; it++) {
            int idx = tid + it * 256;          // 0..1023
            int row = idx >> 3, unit = idx & 7;
            uint32_t soff = (uint32_t)row * 128u + (uint32_t)((unit ^ (row & 7)) << 4);
            int grA = m0 + row;
            int szA = (grA < BN) ? 16 : 0;
            cp16(sb + soff, A + (size_t)grA * K + k0 + unit * 8, szA);
            cp16(sb + 16384 + soff, W + (size_t)(n0 + row) * K + k0 + unit * 8, 16);
        }
        cp_commit();
    };

    float d[2][8][4];
#pragma unroll
    for (int i = 0; i < 2; i++)
#pragma unroll
        for (int j = 0; j < 8; j++)
#pragma unroll
            for (int q = 0; q < 4; q++) d[i][j][q] = 0.f;

    issue(c0, 0);
    for (int cc = 0; cc < NCH; cc++) {
        if (cc + 1 < NCH) { issue(c0 + cc + 1, (cc + 1) & 1); cp_wait<1>(); }
        else              { cp_wait<0>(); }
        __syncthreads();
        uint32_t sb = sbu + (uint32_t)(cc & 1) * STAGE_BYTES;
#pragma unroll
        for (int kk = 0; kk < 4; kk++) {
            uint32_t a[2][4];
#pragma unroll
            for (int mt = 0; mt < 2; mt++) {
                int row = wm0 + mt * 16 + (lane & 15);
                int unit = kk * 2 + (lane >> 4);
                uint32_t off = (uint32_t)row * 128u + (uint32_t)((unit ^ (row & 7)) << 4);
                ldm_x4(a[mt], sb + off);
            }
#pragma unroll
            for (int ng = 0; ng < 4; ng++) {
                int row = wn0 + ng * 16 + (lane & 15);
                int unit = kk * 2 + (lane >> 4);
                uint32_t off = (uint32_t)row * 128u + (uint32_t)((unit ^ (row & 7)) << 4);
                uint32_t b4[4];
                ldm_x4(b4, sb + 16384 + off);
#pragma unroll
                for (int mt = 0; mt < 2; mt++)
#pragma unroll
                    for (int hf = 0; hf < 2; hf++) {
                        mma_f16(d[mt][ng * 2 + hf], a[mt], b4[hf], b4[hf + 2]);
                    }
            }
        }
        __syncthreads();
    }

    // epilogue
#pragma unroll
    for (int mt = 0; mt < 2; mt++) {
#pragma unroll
        for (int half = 0; half < 2; half++) {
            int grow = m0 + wm0 + mt * 16 + (lane >> 2) + half * 8;
            if (grow >= BN) continue;
#pragma unroll
            for (int nt = 0; nt < 8; nt++) {
                int gc = n0 + wn0 + nt * 8 + (lane & 3) * 2;
                float v0 = d[mt][nt][half * 2 + 0];
                float v1 = d[mt][nt][half * 2 + 1];
                size_t o = (size_t)grow * Nn + gc;
                if constexpr (CFG == 0) {
                    *(float2*)&g_qkv[o] = make_float2(v0, v1);
                } else if constexpr (CFG == 1) {
                    atomicAdd(&g_out[o], v0);
                    atomicAdd(&g_out[o + 1], v1);
                } else if constexpr (CFG == 2) {
                    v0 += bias[gc]; v1 += bias[gc + 1];
                    v0 = 0.5f * v0 * (1.0f + erff(v0 * 0.70710678f));
                    v1 = 0.5f * v1 * (1.0f + erff(v1 * 0.70710678f));
                    g_m[o]     = __float2half_rn(v0);
                    g_m[o + 1] = __float2half_rn(v1);
                } else {
                    atomicAdd(&ext_out[o], v0);
                    atomicAdd(&ext_out[o + 1], v1);
                }
            }
        }
    }
}

// ---------------- attention, spatial rows (i >= F): 9 keys each ----------------
__global__ void __launch_bounds__(256) attn_spatial() {
    const float* qkv = g_qkv;
    const int CH = NSP / 8;             // 195
    int bid   = blockIdx.x;
    int chunk = bid % CH;
    int bh    = bid / CH;
    int h     = bh % H_;
    int b     = bh / H_;

    __shared__ float ks[F_][D_], vs[F_][D_];
    int tid = threadIdx.x;
    for (int idx = tid; idx < F_ * D_; idx += 256) {
        int j = idx / D_, dd = idx % D_;
        const float* base = qkv + ((size_t)(b * NTOK + j)) * C3 + h * D_;
        ks[j][dd] = base[C_ + dd];
        vs[j][dd] = base[2 * C_ + dd];
    }
    __syncthreads();

    int warp = tid >> 5, lane = tid & 31;
    int i = F_ + chunk * 8 + warp;
    const float* q = qkv + ((size_t)(b * NTOK + i)) * C3 + h * D_;
    float q0 = q[lane], q1 = q[lane + 32];

    float lg[F_];
#pragma unroll
    for (int j = 0; j < F_; j++) {
        float p = q0 * ks[j][lane] + q1 * ks[j][lane + 32];
#pragma unroll
        for (int off = 16; off; off >>= 1) p += __shfl_xor_sync(0xffffffffu, p, off);
        lg[j] = p * 0.125f;
    }
    float m = lg[0];
#pragma unroll
    for (int j = 1; j < F_; j++) m = fmaxf(m, lg[j]);
    float s = 0.f, a0 = 0.f, a1 = 0.f;
#pragma unroll
    for (int j = 0; j < F_; j++) {
        float w = expf(lg[j] - m);
        s += w;
        a0 += w * vs[j][lane];
        a1 += w * vs[j][lane + 32];
    }
    float inv = 1.0f / s;
    size_t off0 = ((size_t)(b * NTOK + i)) * C_ + h * D_;
    g_at[off0 + lane]      = __float2half_rn(a0 * inv);
    g_at[off0 + lane + 32] = __float2half_rn(a1 * inv);
}

// ---------------- temporal rows: merged split-softmax partials ----------------
__global__ void __launch_bounds__(256) attn_tpart() {
    const float* qkv = g_qkv;
    int bid = blockIdx.x;               // 0 .. B*H*SPLIT-1
    int sp = bid % SPLIT;
    int bh = bid / SPLIT;
    int h  = bh % H_;
    int b  = bh / H_;

    __shared__ float qsh[F_][D_];
    __shared__ float wm[8][F_], ws[8][F_];
    __shared__ float accs[8][F_][D_];
    __shared__ float wlog[8][25][F_];

    int tid = threadIdx.x, w = tid >> 5, lane = tid & 31;
    for (int idx = tid; idx < F_ * D_; idx += 256) {
        int i = idx / D_, dd = idx % D_;
        qsh[i][dd] = qkv[((size_t)(b * NTOK + i)) * C3 + h * D_ + dd];
    }
    __syncthreads();
    float q0[F_], q1[F_];
#pragma unroll
    for (int i = 0; i < F_; i++) { q0[i] = qsh[i][lane]; q1[i] = qsh[i][lane + 32]; }

    int g = sp * 8 + w;                 // global warp 0..63 strides the 1560 keys

    float m[F_], s[F_];
#pragma unroll
    for (int i = 0; i < F_; i++) { m[i] = -1e30f; s[i] = 0.f; }

    int it = 0;
    for (int tt = g; tt < NSP; tt += 64, it++) {
        const float* kp = qkv + ((size_t)(b * NTOK + F_ + tt)) * C3 + C_ + h * D_;
        float k0 = kp[lane], k1 = kp[lane + 32];
#pragma unroll
        for (int i = 0; i < F_; i++) {
            float p = q0[i] * k0 + q1[i] * k1;
#pragma unroll
            for (int off = 16; off; off >>= 1) p += __shfl_xor_sync(0xffffffffu, p, off);
            float lg = p * 0.125f;
            if (lane == 0) wlog[w][it][i] = lg;
            if (lg > m[i]) { s[i] *= expf(m[i] - lg); m[i] = lg; }
            s[i] += expf(lg - m[i]);
        }
    }
    float clslog = 0.f;
    if (g == 0) {
        const float* kp = qkv + ((size_t)(b * NTOK + 0)) * C3 + C_ + h * D_;
        float p = q0[0] * kp[lane] + q1[0] * kp[lane + 32];
#pragma unroll
        for (int off = 16; off; off >>= 1) p += __shfl_xor_sync(0xffffffffu, p, off);
        clslog = p * 0.125f;
        if (clslog > m[0]) { s[0] *= expf(m[0] - clslog); m[0] = clslog; }
        s[0] += expf(clslog - m[0]);
    }
    if (lane == 0) {
#pragma unroll
        for (int i = 0; i < F_; i++) { wm[w][i] = m[i]; ws[w][i] = s[i]; }
    }
    __syncthreads();

    float Mb[F_], Sb[F_];
#pragma unroll
    for (int i = 0; i < F_; i++) {
        float M = wm[0][i];
#pragma unroll
        for (int k = 1; k < 8; k++) M = fmaxf(M, wm[k][i]);
        float S = 0.f;
#pragma unroll
        for (int k = 0; k < 8; k++) S += ws[k][i] * expf(wm[k][i] - M);
        Mb[i] = M; Sb[i] = S;
    }

    float a0[F_], a1[F_];
#pragma unroll
    for (int i = 0; i < F_; i++) { a0[i] = 0.f; a1[i] = 0.f; }
    it = 0;
    for (int tt = g; tt < NSP; tt += 64, it++) {
        const float* vp = qkv + ((size_t)(b * NTOK + F_ + tt)) * C3 + 2 * C_ + h * D_;
        float v0 = vp[lane], v1 = vp[lane + 32];
#pragma unroll
        for (int i = 0; i < F_; i++) {
            float w8 = expf(wlog[w][it][i] - Mb[i]);
            a0[i] += w8 * v0;
            a1[i] += w8 * v1;
        }
    }
    if (g == 0) {
        const float* vp = qkv + ((size_t)(b * NTOK + 0)) * C3 + 2 * C_ + h * D_;
        float w8 = expf(clslog - Mb[0]);
        a0[0] += w8 * vp[lane];
        a1[0] += w8 * vp[lane + 32];
    }
#pragma unroll
    for (int i = 0; i < F_; i++) {
        accs[w][i][lane]      = a0[i];
        accs[w][i][lane + 32] = a1[i];
    }
    __syncthreads();

    for (int idx = tid; idx < F_ * D_; idx += 256) {
        int i = idx / D_, dd = idx % D_;
        float acc = 0.f;
#pragma unroll
        for (int k = 0; k < 8; k++) acc += accs[k][i][dd];
        float* pp = g_part + (size_t)(((bh * F_ + i) * SPLIT) + sp) * 66;
        pp[2 + dd] = acc;
        if (dd == 0) { pp[0] = Mb[i]; pp[1] = Sb[i]; }
    }
}

__global__ void __launch_bounds__(64) attn_tred() {
    int t = blockIdx.x;                 // t = bh*F + i
    int i  = t % F_;
    int bh = t / F_;
    int h = bh % H_;
    int b = bh / H_;
    int d = threadIdx.x;

    float ms[SPLIT], ss[SPLIT];
    float M = -1e30f;
#pragma unroll
    for (int sp = 0; sp < SPLIT; sp++) {
        const float* pp = g_part + (size_t)(t * SPLIT + sp) * 66;
        ms[sp] = pp[0]; ss[sp] = pp[1];
        M = fmaxf(M, ms[sp]);
    }
    float S = 0.f, acc = 0.f;
#pragma unroll
    for (int sp = 0; sp < SPLIT; sp++) {
        float e = expf(ms[sp] - M);
        S += ss[sp] * e;
        acc += g_part[(size_t)(t * SPLIT + sp) * 66 + 2 + d] * e;
    }
    g_at[((size_t)(b * NTOK + i)) * C_ + h * D_ + d] = __float2half_rn(acc / S);
}

// ---------------- launch ----------------
extern "C" void kernel_launch(void* const* d_in, const int* in_sizes, int n_in,
                              void* d_out, int out_size) {
    const float* x     = (const float*)d_in[0];
    const float* ln_g  = (const float*)d_in[1];
    const float* ln_b  = (const float*)d_in[2];
    const float* qkvw  = (const float*)d_in[3];
    const float* projw = (const float*)d_in[4];
    const float* projb = (const float*)d_in[5];
    const float* fc1w  = (const float*)d_in[6];
    const float* fc1b  = (const float*)d_in[7];
    const float* fc2w  = (const float*)d_in[8];
    const float* fc2b  = (const float*)d_in[9];
    float* out = (float*)d_out;

    cudaFuncSetAttribute(gemm_mma<0>, cudaFuncAttributeMaxDynamicSharedMemorySize, SMEM_DYN);
    cudaFuncSetAttribute(gemm_mma<1>, cudaFuncAttributeMaxDynamicSharedMemorySize, SMEM_DYN);
    cudaFuncSetAttribute(gemm_mma<2>, cudaFuncAttributeMaxDynamicSharedMemorySize, SMEM_DYN);
    cudaFuncSetAttribute(gemm_mma<3>, cudaFuncAttributeMaxDynamicSharedMemorySize, SMEM_DYN);

    const int INIT_BLOCKS = (BN * C_ / 4 + 255) / 256;

    // fused weight convert (fp16)
    cvt_all<<<(WTOT / 4 + 255) / 256, 256>>>(qkvw, projw, fc1w, fc2w);

    // 1. g_h = fp16(LN(x))
    ln_kernel<false><<<BN, 256>>>(x, ln_g, ln_b);

    // 2. g_qkv = g_h @ qkv_w^T
    gemm_mma<0><<<dim3(C3 / 128, (BN + 127) / 128), 256, SMEM_DYN>>>(nullptr, nullptr);

    // 3. masked attention -> g_at (fp16); also init g_out = proj_b
    attn_spatial<<<B_ * H_ * (NSP / 8), 256>>>();
    attn_tpart<<<B_ * H_ * SPLIT, 256>>>();
    init_out1<<<INIT_BLOCKS, 256>>>(projb);
    attn_tred<<<B_ * H_ * F_, 64>>>();

    // 4. g_out += g_at @ proj_w^T  (split-K=2, atomic)
    gemm_mma<1><<<dim3(C_ / 128, (BN + 127) / 128, 2), 256, SMEM_DYN>>>(nullptr, nullptr);

    // 5. g_h = fp16(LN(g_out))
    ln_kernel<true><<<BN, 256>>>(nullptr, ln_g, ln_b);

    // 6. g_m = fp16(GELU(g_h @ fc1_w^T + fc1_b))
    gemm_mma<2><<<dim3(DFF / 128, (BN + 127) / 128), 256, SMEM_DYN>>>(fc1b, nullptr);

    // 7. out = g_out + fc2_b; out += g_m @ fc2_w^T  (split-K=2, atomic)
    init_out3<<<INIT_BLOCKS, 256>>>(fc2b, out);
    gemm_mma<3><<<dim3(C_ / 128, (BN + 127) / 128, 2), 256, SMEM_DYN>>>(nullptr, out);
}

// round 12
// speedup vs baseline: 1.5940x; 1.0034x over previous
#include <cuda_runtime.h>
#include <cuda_fp16.h>
#include <math.h>
#include <stdint.h>

// ---------------- problem constants ----------------
static constexpr int B_   = 4;
static constexpr int NTOK = 1569;
static constexpr int C_   = 768;
static constexpr int H_   = 12;
static constexpr int D_   = 64;
static constexpr int F_   = 9;            // CLS + 8 temporal tokens
static constexpr int BN   = B_ * NTOK;    // 6276
static constexpr int C3   = 3 * C_;       // 2304
static constexpr int DFF  = 4 * C_;       // 3072
static constexpr int SPLIT = 8;           // temporal-attention key split
static constexpr int NSP  = NTOK - F_;    // 1560 spatial keys

// ---------------- scratch (device globals; no allocs) ----------------
__device__ __align__(16) float g_qkv[BN * C3];        // qkv projection (fp32)
__device__ __align__(16) float g_out[BN * C_];        // proj output ("new x", fp32)
__device__ __align__(16) __half g_h[BN * C_];         // LN out (fp16)
__device__ __align__(16) __half g_at[BN * C_];        // attn out (fp16)
__device__ __align__(16) __half g_m[BN * DFF];        // fc1 out (fp16)
__device__ __align__(16) __half g_wq[C3 * C_];
__device__ __align__(16) __half g_wp[C_ * C_];
__device__ __align__(16) __half g_w1[DFF * C_];
__device__ __align__(16) __half g_w2[C_ * DFF];
__device__ float g_part[B_ * H_ * F_ * SPLIT * 66];   // split-softmax partials

// ---------------- helpers ----------------
__device__ __forceinline__ uint32_t smem_u32(const void* p) {
    uint32_t a;
    asm("{ .reg .u64 t; cvta.to.shared.u64 t, %1; cvt.u32.u64 %0, t; }" : "=r"(a) : "l"(p));
    return a;
}
__device__ __forceinline__ void cp16(uint32_t dst, const void* src, int sz) {
    asm volatile("cp.async.cg.shared.global [%0], [%1], 16, %2;" :: "r"(dst), "l"(src), "r"(sz) : "memory");
}
__device__ __forceinline__ void cp_commit() { asm volatile("cp.async.commit_group;" ::: "memory"); }
template <int N>
__device__ __forceinline__ void cp_wait() { asm volatile("cp.async.wait_group %0;" :: "n"(N) : "memory"); }

__device__ __forceinline__ void ldm_x4(uint32_t* r, uint32_t addr) {
    asm volatile("ldmatrix.sync.aligned.m8n8.x4.shared.b16 {%0,%1,%2,%3}, [%4];"
                 : "=r"(r[0]), "=r"(r[1]), "=r"(r[2]), "=r"(r[3]) : "r"(addr));
}
__device__ __forceinline__ void mma_f16(float* d, const uint32_t* a, uint32_t b0, uint32_t b1) {
    asm volatile("mma.sync.aligned.m16n8k16.row.col.f32.f16.f16.f32 "
                 "{%0,%1,%2,%3}, {%4,%5,%6,%7}, {%8,%9}, {%0,%1,%2,%3};"
                 : "+f"(d[0]), "+f"(d[1]), "+f"(d[2]), "+f"(d[3])
                 : "r"(a[0]), "r"(a[1]), "r"(a[2]), "r"(a[3]), "r"(b0), "r"(b1));
}

// ---------------- fused, vectorized weight convert (fp32 -> fp16) ----------------
static constexpr int WSEG0 = C3 * C_;
static constexpr int WSEG1 = WSEG0 + C_ * C_;
static constexpr int WSEG2 = WSEG1 + DFF * C_;
static constexpr int WTOT  = WSEG2 + C_ * DFF;

__global__ void __launch_bounds__(256) cvt_all(const float* __restrict__ wq,
                                               const float* __restrict__ wp,
                                               const float* __restrict__ w1,
                                               const float* __restrict__ w2) {
    int i4 = (blockIdx.x * 256 + threadIdx.x) * 4;
    if (i4 >= WTOT) return;
    const float* src; __half* dst; int loc;
    if (i4 < WSEG0)      { src = wq; dst = g_wq; loc = i4; }
    else if (i4 < WSEG1) { src = wp; dst = g_wp; loc = i4 - WSEG0; }
    else if (i4 < WSEG2) { src = w1; dst = g_w1; loc = i4 - WSEG1; }
    else                 { src = w2; dst = g_w2; loc = i4 - WSEG2; }
    float4 v = *(const float4*)(src + loc);
    __half2* hp = (__half2*)(dst + loc);
    hp[0] = __halves2half2(__float2half_rn(v.x), __float2half_rn(v.y));
    hp[1] = __halves2half2(__float2half_rn(v.z), __float2half_rn(v.w));
}

// ---------------- output-init kernels (absorb bias / residual for split-K) ----------------
__global__ void __launch_bounds__(256) init_out1(const float* __restrict__ bias) {
    int idx = (blockIdx.x * 256 + threadIdx.x) * 4;
    if (idx < BN * C_) *(float4*)&g_out[idx] = *(const float4*)&bias[idx % C_];
}
__global__ void __launch_bounds__(256) init_out3(const float* __restrict__ bias,
                                                 float* __restrict__ out) {
    int idx = (blockIdx.x * 256 + threadIdx.x) * 4;
    if (idx < BN * C_) {
        float4 g = *(const float4*)&g_out[idx];
        float4 b = *(const float4*)&bias[idx % C_];
        *(float4*)&out[idx] = make_float4(g.x + b.x, g.y + b.y, g.z + b.z, g.w + b.w);
    }
}

// ---------------- LayerNorm -> fp16 into g_h ----------------
template <bool FROM_OUT>
__global__ void __launch_bounds__(256) ln_kernel(const float* __restrict__ ext_in,
                                                 const float* __restrict__ gam,
                                                 const float* __restrict__ bet) {
    const float* in = FROM_OUT ? g_out : ext_in;
    int row = blockIdx.x;
    const float* x = in + (size_t)row * C_;
    int tid = threadIdx.x;
    float v0 = x[tid], v1 = x[tid + 256], v2 = x[tid + 512];
    float s  = v0 + v1 + v2;
    float ss = v0 * v0 + v1 * v1 + v2 * v2;
#pragma unroll
    for (int off = 16; off; off >>= 1) {
        s  += __shfl_xor_sync(0xffffffffu, s, off);
        ss += __shfl_xor_sync(0xffffffffu, ss, off);
    }
    __shared__ float sm[8], sm2[8], stats[2];
    int warp = tid >> 5, lane = tid & 31;
    if (lane == 0) { sm[warp] = s; sm2[warp] = ss; }
    __syncthreads();
    if (tid == 0) {
        float S = 0.f, SS = 0.f;
#pragma unroll
        for (int w = 0; w < 8; w++) { S += sm[w]; SS += sm2[w]; }
        float mean = S * (1.0f / C_);
        float var  = SS * (1.0f / C_) - mean * mean;
        stats[0] = mean;
        stats[1] = rsqrtf(var + 1e-5f);
    }
    __syncthreads();
    float mean = stats[0], rstd = stats[1];
    size_t base = (size_t)row * C_;
#pragma unroll
    for (int t = 0; t < 3; t++) {
        int c = tid + t * 256;
        float v = t == 0 ? v0 : (t == 1 ? v1 : v2);
        float y = (v - mean) * rstd * gam[c] + bet[c];
        g_h[base + c] = __float2half_rn(y);
    }
}

// ---------------- HMMA GEMM: C[M,Nn] = A[M,K] @ W[Nn,K]^T (plain fp16 x fp16) ----------------
// CFG 0: qkv (store)        CFG 1: proj  (split-K=2, atomicAdd into bias-init g_out)
// CFG 2: fc1 (+bias,GELU)   CFG 3: fc2   (split-K=2, atomicAdd into init'd ext_out)
static constexpr int STAGE_BYTES = 32768;   // A 16KB | W 16KB, xor-swizzled
static constexpr int SMEM_DYN = 2 * STAGE_BYTES;   // 64 KB

template <int CFG>
__global__ void __launch_bounds__(256, 2)
gemm_mma(const float* __restrict__ bias, float* __restrict__ ext_out) {
    constexpr int Nn = (CFG == 0) ? C3 : (CFG == 2) ? DFF : C_;
    constexpr int K  = (CFG == 3) ? DFF : C_;
    constexpr bool SK = (CFG == 1 || CFG == 3);
    constexpr int NCH = (K / 64) / (SK ? 2 : 1);

    const __half* A = (CFG == 0 || CFG == 2) ? g_h : (CFG == 1) ? g_at : g_m;
    const __half* W = (CFG == 0) ? g_wq : (CFG == 1) ? g_wp : (CFG == 2) ? g_w1 : g_w2;

    extern __shared__ char smraw[];
    uint32_t sbu = smem_u32(smraw);

    int tid = threadIdx.x, lane = tid & 31, wid = tid >> 5;
    int n0 = blockIdx.x * 128, m0 = blockIdx.y * 128;
    int c0 = SK ? (int)blockIdx.z * NCH : 0;
    int wm0 = (wid & 3) * 32, wn0 = (wid >> 2) * 64;

    auto issue = [&](int c, int s) {
        int k0 = c * 64;
        uint32_t sb = sbu + (uint32_t)s * STAGE_BYTES;
#pragma unroll
        for (int it = 0; it < 4; it++) {
            int idx = tid + it * 256;          // 0..1023
            int row = idx >> 3, unit = idx & 7;
            uint32_t soff = (uint32_t)row * 128u + (uint32_t)((unit ^ (row & 7)) << 4);
            int grA = m0 + row;
            int szA = (grA < BN) ? 16 : 0;
            cp16(sb + soff, A + (size_t)grA * K + k0 + unit * 8, szA);
            cp16(sb + 16384 + soff, W + (size_t)(n0 + row) * K + k0 + unit * 8, 16);
        }
        cp_commit();
    };

    float d[2][8][4];
#pragma unroll
    for (int i = 0; i < 2; i++)
#pragma unroll
        for (int j = 0; j < 8; j++)
#pragma unroll
            for (int q = 0; q < 4; q++) d[i][j][q] = 0.f;

    issue(c0, 0);
    for (int cc = 0; cc < NCH; cc++) {
        if (cc + 1 < NCH) { issue(c0 + cc + 1, (cc + 1) & 1); cp_wait<1>(); }
        else              { cp_wait<0>(); }
        __syncthreads();
        uint32_t sb = sbu + (uint32_t)(cc & 1) * STAGE_BYTES;
#pragma unroll
        for (int kk = 0; kk < 4; kk++) {
            uint32_t a[2][4];
#pragma unroll
            for (int mt = 0; mt < 2; mt++) {
                int row = wm0 + mt * 16 + (lane & 15);
                int unit = kk * 2 + (lane >> 4);
                uint32_t off = (uint32_t)row * 128u + (uint32_t)((unit ^ (row & 7)) << 4);
                ldm_x4(a[mt], sb + off);
            }
#pragma unroll
            for (int ng = 0; ng < 4; ng++) {
                int row = wn0 + ng * 16 + (lane & 15);
                int unit = kk * 2 + (lane >> 4);
                uint32_t off = (uint32_t)row * 128u + (uint32_t)((unit ^ (row & 7)) << 4);
                uint32_t b4[4];
                ldm_x4(b4, sb + 16384 + off);
#pragma unroll
                for (int mt = 0; mt < 2; mt++)
#pragma unroll
                    for (int hf = 0; hf < 2; hf++) {
                        mma_f16(d[mt][ng * 2 + hf], a[mt], b4[hf], b4[hf + 2]);
                    }
            }
        }
        __syncthreads();
    }

    // epilogue
#pragma unroll
    for (int mt = 0; mt < 2; mt++) {
#pragma unroll
        for (int half = 0; half < 2; half++) {
            int grow = m0 + wm0 + mt * 16 + (lane >> 2) + half * 8;
            if (grow >= BN) continue;
#pragma unroll
            for (int nt = 0; nt < 8; nt++) {
                int gc = n0 + wn0 + nt * 8 + (lane & 3) * 2;
                float v0 = d[mt][nt][half * 2 + 0];
                float v1 = d[mt][nt][half * 2 + 1];
                size_t o = (size_t)grow * Nn + gc;
                if constexpr (CFG == 0) {
                    *(float2*)&g_qkv[o] = make_float2(v0, v1);
                } else if constexpr (CFG == 1) {
                    atomicAdd(&g_out[o], v0);
                    atomicAdd(&g_out[o + 1], v1);
                } else if constexpr (CFG == 2) {
                    v0 += bias[gc]; v1 += bias[gc + 1];
                    v0 = 0.5f * v0 * (1.0f + erff(v0 * 0.70710678f));
                    v1 = 0.5f * v1 * (1.0f + erff(v1 * 0.70710678f));
                    g_m[o]     = __float2half_rn(v0);
                    g_m[o + 1] = __float2half_rn(v1);
                } else {
                    atomicAdd(&ext_out[o], v0);
                    atomicAdd(&ext_out[o + 1], v1);
                }
            }
        }
    }
}

// ---------------- attention, spatial rows (i >= F): 9 keys each ----------------
__global__ void __launch_bounds__(256) attn_spatial() {
    const float* qkv = g_qkv;
    const int CH = NSP / 8;             // 195
    int bid   = blockIdx.x;
    int chunk = bid % CH;
    int bh    = bid / CH;
    int h     = bh % H_;
    int b     = bh / H_;

    __shared__ float ks[F_][D_], vs[F_][D_];
    int tid = threadIdx.x;
    for (int idx = tid; idx < F_ * D_; idx += 256) {
        int j = idx / D_, dd = idx % D_;
        const float* base = qkv + ((size_t)(b * NTOK + j)) * C3 + h * D_;
        ks[j][dd] = base[C_ + dd];
        vs[j][dd] = base[2 * C_ + dd];
    }
    __syncthreads();

    int warp = tid >> 5, lane = tid & 31;
    int i = F_ + chunk * 8 + warp;
    const float* q = qkv + ((size_t)(b * NTOK + i)) * C3 + h * D_;
    float q0 = q[lane], q1 = q[lane + 32];

    float lg[F_];
#pragma unroll
    for (int j = 0; j < F_; j++) {
        float p = q0 * ks[j][lane] + q1 * ks[j][lane + 32];
#pragma unroll
        for (int off = 16; off; off >>= 1) p += __shfl_xor_sync(0xffffffffu, p, off);
        lg[j] = p * 0.125f;
    }
    float m = lg[0];
#pragma unroll
    for (int j = 1; j < F_; j++) m = fmaxf(m, lg[j]);
    float s = 0.f, a0 = 0.f, a1 = 0.f;
#pragma unroll
    for (int j = 0; j < F_; j++) {
        float w = expf(lg[j] - m);
        s += w;
        a0 += w * vs[j][lane];
        a1 += w * vs[j][lane + 32];
    }
    float inv = 1.0f / s;
    size_t off0 = ((size_t)(b * NTOK + i)) * C_ + h * D_;
    g_at[off0 + lane]      = __float2half_rn(a0 * inv);
    g_at[off0 + lane + 32] = __float2half_rn(a1 * inv);
}

// ---------------- temporal rows: merged split-softmax partials ----------------
__global__ void __launch_bounds__(256) attn_tpart() {
    const float* qkv = g_qkv;
    int bid = blockIdx.x;               // 0 .. B*H*SPLIT-1
    int sp = bid % SPLIT;
    int bh = bid / SPLIT;
    int h  = bh % H_;
    int b  = bh / H_;

    __shared__ float qsh[F_][D_];
    __shared__ float wm[8][F_], ws[8][F_];
    __shared__ float accs[8][F_][D_];
    __shared__ float wlog[8][25][F_];

    int tid = threadIdx.x, w = tid >> 5, lane = tid & 31;
    for (int idx = tid; idx < F_ * D_; idx += 256) {
        int i = idx / D_, dd = idx % D_;
        qsh[i][dd] = qkv[((size_t)(b * NTOK + i)) * C3 + h * D_ + dd];
    }
    __syncthreads();
    float q0[F_], q1[F_];
#pragma unroll
    for (int i = 0; i < F_; i++) { q0[i] = qsh[i][lane]; q1[i] = qsh[i][lane + 32]; }

    int g = sp * 8 + w;                 // global warp 0..63 strides the 1560 keys

    float m[F_], s[F_];
#pragma unroll
    for (int i = 0; i < F_; i++) { m[i] = -1e30f; s[i] = 0.f; }

    int it = 0;
    for (int tt = g; tt < NSP; tt += 64, it++) {
        const float* kp = qkv + ((size_t)(b * NTOK + F_ + tt)) * C3 + C_ + h * D_;
        float k0 = kp[lane], k1 = kp[lane + 32];
#pragma unroll
        for (int i = 0; i < F_; i++) {
            float p = q0[i] * k0 + q1[i] * k1;
#pragma unroll
            for (int off = 16; off; off >>= 1) p += __shfl_xor_sync(0xffffffffu, p, off);
            float lg = p * 0.125f;
            if (lane == 0) wlog[w][it][i] = lg;
            if (lg > m[i]) { s[i] *= expf(m[i] - lg); m[i] = lg; }
            s[i] += expf(lg - m[i]);
        }
    }
    float clslog = 0.f;
    if (g == 0) {
        const float* kp = qkv + ((size_t)(b * NTOK + 0)) * C3 + C_ + h * D_;
        float p = q0[0] * kp[lane] + q1[0] * kp[lane + 32];
#pragma unroll
        for (int off = 16; off; off >>= 1) p += __shfl_xor_sync(0xffffffffu, p, off);
        clslog = p * 0.125f;
        if (clslog > m[0]) { s[0] *= expf(m[0] - clslog); m[0] = clslog; }
        s[0] += expf(clslog - m[0]);
    }
    if (lane == 0) {
#pragma unroll
        for (int i = 0; i < F_; i++) { wm[w][i] = m[i]; ws[w][i] = s[i]; }
    }
    __syncthreads();

    float Mb[F_], Sb[F_];
#pragma unroll
    for (int i = 0; i < F_; i++) {
        float M = wm[0][i];
#pragma unroll
        for (int k = 1; k < 8; k++) M = fmaxf(M, wm[k][i]);
        float S = 0.f;
#pragma unroll
        for (int k = 0; k < 8; k++) S += ws[k][i] * expf(wm[k][i] - M);
        Mb[i] = M; Sb[i] = S;
    }

    float a0[F_], a1[F_];
#pragma unroll
    for (int i = 0; i < F_; i++) { a0[i] = 0.f; a1[i] = 0.f; }
    it = 0;
    for (int tt = g; tt < NSP; tt += 64, it++) {
        const float* vp = qkv + ((size_t)(b * NTOK + F_ + tt)) * C3 + 2 * C_ + h * D_;
        float v0 = vp[lane], v1 = vp[lane + 32];
#pragma unroll
        for (int i = 0; i < F_; i++) {
            float w8 = expf(wlog[w][it][i] - Mb[i]);
            a0[i] += w8 * v0;
            a1[i] += w8 * v1;
        }
    }
    if (g == 0) {
        const float* vp = qkv + ((size_t)(b * NTOK + 0)) * C3 + 2 * C_ + h * D_;
        float w8 = expf(clslog - Mb[0]);
        a0[0] += w8 * vp[lane];
        a1[0] += w8 * vp[lane + 32];
    }
#pragma unroll
    for (int i = 0; i < F_; i++) {
        accs[w][i][lane]      = a0[i];
        accs[w][i][lane + 32] = a1[i];
    }
    __syncthreads();

    for (int idx = tid; idx < F_ * D_; idx += 256) {
        int i = idx / D_, dd = idx % D_;
        float acc = 0.f;
#pragma unroll
        for (int k = 0; k < 8; k++) acc += accs[k][i][dd];
        float* pp = g_part + (size_t)(((bh * F_ + i) * SPLIT) + sp) * 66;
        pp[2 + dd] = acc;
        if (dd == 0) { pp[0] = Mb[i]; pp[1] = Sb[i]; }
    }
}

__global__ void __launch_bounds__(64) attn_tred() {
    int t = blockIdx.x;                 // t = bh*F + i
    int i  = t % F_;
    int bh = t / F_;
    int h = bh % H_;
    int b = bh / H_;
    int d = threadIdx.x;

    float ms[SPLIT], ss[SPLIT];
    float M = -1e30f;
#pragma unroll
    for (int sp = 0; sp < SPLIT; sp++) {
        const float* pp = g_part + (size_t)(t * SPLIT + sp) * 66;
        ms[sp] = pp[0]; ss[sp] = pp[1];
        M = fmaxf(M, ms[sp]);
    }
    float S = 0.f, acc = 0.f;
#pragma unroll
    for (int sp = 0; sp < SPLIT; sp++) {
        float e = expf(ms[sp] - M);
        S += ss[sp] * e;
        acc += g_part[(size_t)(t * SPLIT + sp) * 66 + 2 + d] * e;
    }
    g_at[((size_t)(b * NTOK + i)) * C_ + h * D_ + d] = __float2half_rn(acc / S);
}

// ---------------- launch (stream fork/join, capture-safe) ----------------
extern "C" void kernel_launch(void* const* d_in, const int* in_sizes, int n_in,
                              void* d_out, int out_size) {
    const float* x     = (const float*)d_in[0];
    const float* ln_g  = (const float*)d_in[1];
    const float* ln_b  = (const float*)d_in[2];
    const float* qkvw  = (const float*)d_in[3];
    const float* projw = (const float*)d_in[4];
    const float* projb = (const float*)d_in[5];
    const float* fc1w  = (const float*)d_in[6];
    const float* fc1b  = (const float*)d_in[7];
    const float* fc2w  = (const float*)d_in[8];
    const float* fc2b  = (const float*)d_in[9];
    float* out = (float*)d_out;

    cudaFuncSetAttribute(gemm_mma<0>, cudaFuncAttributeMaxDynamicSharedMemorySize, SMEM_DYN);
    cudaFuncSetAttribute(gemm_mma<1>, cudaFuncAttributeMaxDynamicSharedMemorySize, SMEM_DYN);
    cudaFuncSetAttribute(gemm_mma<2>, cudaFuncAttributeMaxDynamicSharedMemorySize, SMEM_DYN);
    cudaFuncSetAttribute(gemm_mma<3>, cudaFuncAttributeMaxDynamicSharedMemorySize, SMEM_DYN);

    // side stream + events (host objects, no device memory; created per call,
    // intentionally leaked — kernel_launch is invoked only a handful of times
    // and graph REPLAYS do not re-run this host code)
    cudaStream_t s2;
    cudaStreamCreateWithFlags(&s2, cudaStreamNonBlocking);
    cudaEvent_t e0, e1, e2, e3, e4, e5;
    cudaEventCreateWithFlags(&e0, cudaEventDisableTiming);
    cudaEventCreateWithFlags(&e1, cudaEventDisableTiming);
    cudaEventCreateWithFlags(&e2, cudaEventDisableTiming);
    cudaEventCreateWithFlags(&e3, cudaEventDisableTiming);
    cudaEventCreateWithFlags(&e4, cudaEventDisableTiming);
    cudaEventCreateWithFlags(&e5, cudaEventDisableTiming);

    const int INIT_BLOCKS = (BN * C_ / 4 + 255) / 256;
    cudaStream_t m = 0;   // main (capture-origin) stream

    // ---- fork 1: ln1 (s2)  ||  cvt_all (main) ----
    cudaEventRecord(e0, m);
    cudaStreamWaitEvent(s2, e0, 0);
    ln_kernel<false><<<BN, 256, 0, s2>>>(x, ln_g, ln_b);
    cvt_all<<<(WTOT / 4 + 255) / 256, 256, 0, m>>>(qkvw, projw, fc1w, fc2w);
    cudaEventRecord(e1, s2);
    cudaStreamWaitEvent(m, e1, 0);

    // 2. g_qkv = g_h @ qkv_w^T
    gemm_mma<0><<<dim3(C3 / 128, (BN + 127) / 128), 256, SMEM_DYN, m>>>(nullptr, nullptr);

    // ---- fork 2: tpart->tred (s2)  ||  spatial + init_out1 (main) ----
    cudaEventRecord(e2, m);
    cudaStreamWaitEvent(s2, e2, 0);
    attn_tpart<<<B_ * H_ * SPLIT, 256, 0, s2>>>();
    attn_tred<<<B_ * H_ * F_, 64, 0, s2>>>();
    attn_spatial<<<B_ * H_ * (NSP / 8), 256, 0, m>>>();
    init_out1<<<INIT_BLOCKS, 256, 0, m>>>(projb);
    cudaEventRecord(e3, s2);
    cudaStreamWaitEvent(m, e3, 0);

    // 4. g_out += g_at @ proj_w^T  (split-K=2, atomic)
    gemm_mma<1><<<dim3(C_ / 128, (BN + 127) / 128, 2), 256, SMEM_DYN, m>>>(nullptr, nullptr);

    // ---- fork 3: init_out3 (s2)  ||  ln2 + fc1 (main) ----
    cudaEventRecord(e4, m);
    cudaStreamWaitEvent(s2, e4, 0);
    init_out3<<<INIT_BLOCKS, 256, 0, s2>>>(fc2b, out);
    ln_kernel<true><<<BN, 256, 0, m>>>(nullptr, ln_g, ln_b);
    gemm_mma<2><<<dim3(DFF / 128, (BN + 127) / 128), 256, SMEM_DYN, m>>>(fc1b, nullptr);
    cudaEventRecord(e5, s2);
    cudaStreamWaitEvent(m, e5, 0);

    // 7. out += g_m @ fc2_w^T  (split-K=2, atomic)
    gemm_mma<3><<<dim3(C_ / 128, (BN + 127) / 128, 2), 256, SMEM_DYN, m>>>(nullptr, out);
}

// round 13
// speedup vs baseline: 1.7730x; 1.1123x over previous
#include <cuda_runtime.h>
#include <cuda_fp16.h>
#include <math.h>
#include <stdint.h>

// ---------------- problem constants ----------------
static constexpr int B_   = 4;
static constexpr int NTOK = 1569;
static constexpr int C_   = 768;
static constexpr int H_   = 12;
static constexpr int D_   = 64;
static constexpr int F_   = 9;            // CLS + 8 temporal tokens
static constexpr int BN   = B_ * NTOK;    // 6276
static constexpr int C3   = 3 * C_;       // 2304
static constexpr int DFF  = 4 * C_;       // 3072
static constexpr int SPLIT = 12;          // temporal-attention key split
static constexpr int NSP  = NTOK - F_;    // 1560 spatial keys
static constexpr int KPB  = NSP / SPLIT;  // 130 keys per block

// ---------------- scratch (device globals; no allocs) ----------------
__device__ __align__(16) float g_qkv[BN * C3];        // qkv projection (fp32)
__device__ __align__(16) float g_out[BN * C_];        // proj output ("new x", fp32)
__device__ __align__(16) __half g_h[BN * C_];         // LN out (fp16)
__device__ __align__(16) __half g_at[BN * C_];        // attn out (fp16)
__device__ __align__(16) __half g_m[BN * DFF];        // fc1 out (fp16)
__device__ __align__(16) __half g_wq[C3 * C_];
__device__ __align__(16) __half g_wp[C_ * C_];
__device__ __align__(16) __half g_w1[DFF * C_];
__device__ __align__(16) __half g_w2[C_ * DFF];
__device__ float g_part[B_ * H_ * F_ * SPLIT * 66];   // split-softmax partials

// ---------------- helpers ----------------
__device__ __forceinline__ uint32_t smem_u32(const void* p) {
    uint32_t a;
    asm("{ .reg .u64 t; cvta.to.shared.u64 t, %1; cvt.u32.u64 %0, t; }" : "=r"(a) : "l"(p));
    return a;
}
__device__ __forceinline__ void cp16(uint32_t dst, const void* src, int sz) {
    asm volatile("cp.async.cg.shared.global [%0], [%1], 16, %2;" :: "r"(dst), "l"(src), "r"(sz) : "memory");
}
__device__ __forceinline__ void cp_commit() { asm volatile("cp.async.commit_group;" ::: "memory"); }
template <int N>
__device__ __forceinline__ void cp_wait() { asm volatile("cp.async.wait_group %0;" :: "n"(N) : "memory"); }

__device__ __forceinline__ void ldm_x4(uint32_t* r, uint32_t addr) {
    asm volatile("ldmatrix.sync.aligned.m8n8.x4.shared.b16 {%0,%1,%2,%3}, [%4];"
                 : "=r"(r[0]), "=r"(r[1]), "=r"(r[2]), "=r"(r[3]) : "r"(addr));
}
__device__ __forceinline__ void mma_f16(float* d, const uint32_t* a, uint32_t b0, uint32_t b1) {
    asm volatile("mma.sync.aligned.m16n8k16.row.col.f32.f16.f16.f32 "
                 "{%0,%1,%2,%3}, {%4,%5,%6,%7}, {%8,%9}, {%0,%1,%2,%3};"
                 : "+f"(d[0]), "+f"(d[1]), "+f"(d[2]), "+f"(d[3])
                 : "r"(a[0]), "r"(a[1]), "r"(a[2]), "r"(a[3]), "r"(b0), "r"(b1));
}

// ---------------- fused, vectorized weight convert (fp32 -> fp16) ----------------
static constexpr int WSEG0 = C3 * C_;
static constexpr int WSEG1 = WSEG0 + C_ * C_;
static constexpr int WSEG2 = WSEG1 + DFF * C_;
static constexpr int WTOT  = WSEG2 + C_ * DFF;

__global__ void __launch_bounds__(256) cvt_all(const float* __restrict__ wq,
                                               const float* __restrict__ wp,
                                               const float* __restrict__ w1,
                                               const float* __restrict__ w2) {
    int i4 = (blockIdx.x * 256 + threadIdx.x) * 4;
    if (i4 >= WTOT) return;
    const float* src; __half* dst; int loc;
    if (i4 < WSEG0)      { src = wq; dst = g_wq; loc = i4; }
    else if (i4 < WSEG1) { src = wp; dst = g_wp; loc = i4 - WSEG0; }
    else if (i4 < WSEG2) { src = w1; dst = g_w1; loc = i4 - WSEG1; }
    else                 { src = w2; dst = g_w2; loc = i4 - WSEG2; }
    float4 v = *(const float4*)(src + loc);
    __half2* hp = (__half2*)(dst + loc);
    hp[0] = __halves2half2(__float2half_rn(v.x), __float2half_rn(v.y));
    hp[1] = __halves2half2(__float2half_rn(v.z), __float2half_rn(v.w));
}

// ---------------- output-init kernels (absorb bias / residual for split-K) ----------------
__global__ void __launch_bounds__(256) init_out1(const float* __restrict__ bias) {
    int idx = (blockIdx.x * 256 + threadIdx.x) * 4;
    if (idx < BN * C_) *(float4*)&g_out[idx] = *(const float4*)&bias[idx % C_];
}
__global__ void __launch_bounds__(256) init_out3(const float* __restrict__ bias,
                                                 float* __restrict__ out) {
    int idx = (blockIdx.x * 256 + threadIdx.x) * 4;
    if (idx < BN * C_) {
        float4 g = *(const float4*)&g_out[idx];
        float4 b = *(const float4*)&bias[idx % C_];
        *(float4*)&out[idx] = make_float4(g.x + b.x, g.y + b.y, g.z + b.z, g.w + b.w);
    }
}

// ---------------- LayerNorm -> fp16 into g_h ----------------
template <bool FROM_OUT>
__global__ void __launch_bounds__(256) ln_kernel(const float* __restrict__ ext_in,
                                                 const float* __restrict__ gam,
                                                 const float* __restrict__ bet) {
    const float* in = FROM_OUT ? g_out : ext_in;
    int row = blockIdx.x;
    const float* x = in + (size_t)row * C_;
    int tid = threadIdx.x;
    float v0 = x[tid], v1 = x[tid + 256], v2 = x[tid + 512];
    float s  = v0 + v1 + v2;
    float ss = v0 * v0 + v1 * v1 + v2 * v2;
#pragma unroll
    for (int off = 16; off; off >>= 1) {
        s  += __shfl_xor_sync(0xffffffffu, s, off);
        ss += __shfl_xor_sync(0xffffffffu, ss, off);
    }
    __shared__ float sm[8], sm2[8], stats[2];
    int warp = tid >> 5, lane = tid & 31;
    if (lane == 0) { sm[warp] = s; sm2[warp] = ss; }
    __syncthreads();
    if (tid == 0) {
        float S = 0.f, SS = 0.f;
#pragma unroll
        for (int w = 0; w < 8; w++) { S += sm[w]; SS += sm2[w]; }
        float mean = S * (1.0f / C_);
        float var  = SS * (1.0f / C_) - mean * mean;
        stats[0] = mean;
        stats[1] = rsqrtf(var + 1e-5f);
    }
    __syncthreads();
    float mean = stats[0], rstd = stats[1];
    size_t base = (size_t)row * C_;
#pragma unroll
    for (int t = 0; t < 3; t++) {
        int c = tid + t * 256;
        float v = t == 0 ? v0 : (t == 1 ? v1 : v2);
        float y = (v - mean) * rstd * gam[c] + bet[c];
        g_h[base + c] = __float2half_rn(y);
    }
}

// ---------------- HMMA GEMM: C[M,Nn] = A[M,K] @ W[Nn,K]^T (plain fp16 x fp16) ----------------
static constexpr int STAGE_BYTES = 32768;   // A 16KB | W 16KB, xor-swizzled
static constexpr int SMEM_DYN = 2 * STAGE_BYTES;   // 64 KB

template <int CFG>
__global__ void __launch_bounds__(256, 2)
gemm_mma(const float* __restrict__ bias, float* __restrict__ ext_out) {
    constexpr int Nn = (CFG == 0) ? C3 : (CFG == 2) ? DFF : C_;
    constexpr int K  = (CFG == 3) ? DFF : C_;
    constexpr bool SK = (CFG == 1 || CFG == 3);
    constexpr int NCH = (K / 64) / (SK ? 2 : 1);

    const __half* A = (CFG == 0 || CFG == 2) ? g_h : (CFG == 1) ? g_at : g_m;
    const __half* W = (CFG == 0) ? g_wq : (CFG == 1) ? g_wp : (CFG == 2) ? g_w1 : g_w2;

    extern __shared__ char smraw[];
    uint32_t sbu = smem_u32(smraw);

    int tid = threadIdx.x, lane = tid & 31, wid = tid >> 5;
    int n0 = blockIdx.x * 128, m0 = blockIdx.y * 128;
    int c0 = SK ? (int)blockIdx.z * NCH : 0;
    int wm0 = (wid & 3) * 32, wn0 = (wid >> 2) * 64;

    auto issue = [&](int c, int s) {
        int k0 = c * 64;
        uint32_t sb = sbu + (uint32_t)s * STAGE_BYTES;
#pragma unroll
        for (int it = 0; it < 4; it++) {
            int idx = tid + it * 256;          // 0..1023
            int row = idx >> 3, unit = idx & 7;
            uint32_t soff = (uint32_t)row * 128u + (uint32_t)((unit ^ (row & 7)) << 4);
            int grA = m0 + row;
            int szA = (grA < BN) ? 16 : 0;
            cp16(sb + soff, A + (size_t)grA * K + k0 + unit * 8, szA);
            cp16(sb + 16384 + soff, W + (size_t)(n0 + row) * K + k0 + unit * 8, 16);
        }
        cp_commit();
    };

    float d[2][8][4];
#pragma unroll
    for (int i = 0; i < 2; i++)
#pragma unroll
        for (int j = 0; j < 8; j++)
#pragma unroll
            for (int q = 0; q < 4; q++) d[i][j][q] = 0.f;

    issue(c0, 0);
    for (int cc = 0; cc < NCH; cc++) {
        if (cc + 1 < NCH) { issue(c0 + cc + 1, (cc + 1) & 1); cp_wait<1>(); }
        else              { cp_wait<0>(); }
        __syncthreads();
        uint32_t sb = sbu + (uint32_t)(cc & 1) * STAGE_BYTES;
#pragma unroll
        for (int kk = 0; kk < 4; kk++) {
            uint32_t a[2][4];
#pragma unroll
            for (int mt = 0; mt < 2; mt++) {
                int row = wm0 + mt * 16 + (lane & 15);
                int unit = kk * 2 + (lane >> 4);
                uint32_t off = (uint32_t)row * 128u + (uint32_t)((unit ^ (row & 7)) << 4);
                ldm_x4(a[mt], sb + off);
            }
#pragma unroll
            for (int ng = 0; ng < 4; ng++) {
                int row = wn0 + ng * 16 + (lane & 15);
                int unit = kk * 2 + (lane >> 4);
                uint32_t off = (uint32_t)row * 128u + (uint32_t)((unit ^ (row & 7)) << 4);
                uint32_t b4[4];
                ldm_x4(b4, sb + 16384 + off);
#pragma unroll
                for (int mt = 0; mt < 2; mt++)
#pragma unroll
                    for (int hf = 0; hf < 2; hf++) {
                        mma_f16(d[mt][ng * 2 + hf], a[mt], b4[hf], b4[hf + 2]);
                    }
            }
        }
        __syncthreads();
    }

    // epilogue
#pragma unroll
    for (int mt = 0; mt < 2; mt++) {
#pragma unroll
        for (int half = 0; half < 2; half++) {
            int grow = m0 + wm0 + mt * 16 + (lane >> 2) + half * 8;
            if (grow >= BN) continue;
#pragma unroll
            for (int nt = 0; nt < 8; nt++) {
                int gc = n0 + wn0 + nt * 8 + (lane & 3) * 2;
                float v0 = d[mt][nt][half * 2 + 0];
                float v1 = d[mt][nt][half * 2 + 1];
                size_t o = (size_t)grow * Nn + gc;
                if constexpr (CFG == 0) {
                    *(float2*)&g_qkv[o] = make_float2(v0, v1);
                } else if constexpr (CFG == 1) {
                    atomicAdd(&g_out[o], v0);
                    atomicAdd(&g_out[o + 1], v1);
                } else if constexpr (CFG == 2) {
                    v0 += bias[gc]; v1 += bias[gc + 1];
                    v0 = 0.5f * v0 * (1.0f + erff(v0 * 0.70710678f));
                    v1 = 0.5f * v1 * (1.0f + erff(v1 * 0.70710678f));
                    g_m[o]     = __float2half_rn(v0);
                    g_m[o + 1] = __float2half_rn(v1);
                } else {
                    atomicAdd(&ext_out[o], v0);
                    atomicAdd(&ext_out[o + 1], v1);
                }
            }
        }
    }
}

// ---------------- attention, spatial rows (i >= F): 9 keys each ----------------
__global__ void __launch_bounds__(256) attn_spatial() {
    const float* qkv = g_qkv;
    const int CH = NSP / 8;             // 195
    int bid   = blockIdx.x;
    int chunk = bid % CH;
    int bh    = bid / CH;
    int h     = bh % H_;
    int b     = bh / H_;

    __shared__ float ks[F_][D_], vs[F_][D_];
    int tid = threadIdx.x;
    for (int idx = tid; idx < F_ * D_; idx += 256) {
        int j = idx / D_, dd = idx % D_;
        const float* base = qkv + ((size_t)(b * NTOK + j)) * C3 + h * D_;
        ks[j][dd] = base[C_ + dd];
        vs[j][dd] = base[2 * C_ + dd];
    }
    __syncthreads();

    int warp = tid >> 5, lane = tid & 31;
    int i = F_ + chunk * 8 + warp;
    const float* q = qkv + ((size_t)(b * NTOK + i)) * C3 + h * D_;
    float q0 = q[lane], q1 = q[lane + 32];

    float lg[F_];
#pragma unroll
    for (int j = 0; j < F_; j++) {
        float p = q0 * ks[j][lane] + q1 * ks[j][lane + 32];
#pragma unroll
        for (int off = 16; off; off >>= 1) p += __shfl_xor_sync(0xffffffffu, p, off);
        lg[j] = p * 0.125f;
    }
    float m = lg[0];
#pragma unroll
    for (int j = 1; j < F_; j++) m = fmaxf(m, lg[j]);
    float s = 0.f, a0 = 0.f, a1 = 0.f;
#pragma unroll
    for (int j = 0; j < F_; j++) {
        float w = expf(lg[j] - m);
        s += w;
        a0 += w * vs[j][lane];
        a1 += w * vs[j][lane + 32];
    }
    float inv = 1.0f / s;
    size_t off0 = ((size_t)(b * NTOK + i)) * C_ + h * D_;
    g_at[off0 + lane]      = __float2half_rn(a0 * inv);
    g_at[off0 + lane + 32] = __float2half_rn(a1 * inv);
}

// ---------------- temporal rows: smem-tiled thread-per-key partials ----------------
// grid = B*H*SPLIT; block handles KPB=130 keys (+CLS for sp==0) for ALL 9 rows.
__global__ void __launch_bounds__(256) attn_tpart() {
    const float* qkv = g_qkv;
    int bid = blockIdx.x;
    int sp = bid % SPLIT;
    int bh = bid / SPLIT;
    int h  = bh % H_;
    int b  = bh / H_;

    __shared__ float qsh[F_][D_];            // 2.3 KB
    __shared__ float kt[KPB + 1][D_ + 3];    // 131 x 67 fp32 = 35.1 KB (pitch 67: conflict-free)
    __shared__ float lgs[KPB + 1][F_];       // 4.7 KB (stride 9: conflict-free)
    __shared__ float red[F_][2];             // Mb, Sb

    int tid = threadIdx.x, w = tid >> 5, lane = tid & 31;
    int base = F_ + sp * KPB;
    int cnt = KPB + (sp == 0 ? 1 : 0);

    // stage Q and K tile (coalesced global reads)
    for (int idx = tid; idx < F_ * D_; idx += 256)
        qsh[idx / D_][idx % D_] = qkv[((size_t)(b * NTOK + idx / D_)) * C3 + h * D_ + idx % D_];
    for (int idx = tid; idx < KPB * D_; idx += 256) {
        int j = idx / D_, d = idx % D_;
        kt[j][d] = qkv[((size_t)(b * NTOK + base + j)) * C3 + C_ + h * D_ + d];
    }
    if (sp == 0)
        for (int d = tid; d < D_; d += 256)
            kt[KPB][d] = qkv[((size_t)(b * NTOK + 0)) * C3 + C_ + h * D_ + d];
    __syncthreads();

    // pass 1: thread t = key t; all 9 logits, no shuffles
    if (tid < cnt) {
        float acc[F_];
#pragma unroll
        for (int i = 0; i < F_; i++) acc[i] = 0.f;
        for (int d = 0; d < D_; d++) {
            float kd = kt[tid][d];
#pragma unroll
            for (int i = 0; i < F_; i++) acc[i] += qsh[i][d] * kd;
        }
        bool cls = (tid == KPB);
#pragma unroll
        for (int i = 0; i < F_; i++)
            lgs[tid][i] = (cls && i > 0) ? -1e30f : acc[i] * 0.125f;
    }
    __syncthreads();

    // per-row block max / expsum (warp r handles row r; warp 0 also row 8)
    for (int r = w; r < F_; r += 8) {
        float mx = -1e30f, sm = 0.f;
        for (int t = lane; t < cnt; t += 32) {
            float lg = lgs[t][r];
            if (lg > mx) { sm *= expf(mx - lg); mx = lg; }
            sm += expf(lg - mx);
        }
#pragma unroll
        for (int off = 16; off; off >>= 1) {
            float mo = __shfl_xor_sync(0xffffffffu, mx, off);
            float so = __shfl_xor_sync(0xffffffffu, sm, off);
            float Mx = fmaxf(mx, mo);
            sm = sm * expf(mx - Mx) + so * expf(mo - Mx);
            mx = Mx;
        }
        if (lane == 0) { red[r][0] = mx; red[r][1] = sm; }
    }
    __syncthreads();

    // pass 2: warp w owns row w (warp 0 also row 8); V rows L1-resident
    for (int r = w; r < F_; r += 8) {
        float M = red[r][0];
        float a0 = 0.f, a1 = 0.f;
        for (int t = 0; t < cnt; t++) {
            float w8 = expf(lgs[t][r] - M);
            int j = (t == KPB) ? 0 : base + t;
            const float* vp = qkv + ((size_t)(b * NTOK + j)) * C3 + 2 * C_ + h * D_;
            a0 += w8 * vp[lane];
            a1 += w8 * vp[lane + 32];
        }
        float* pp = g_part + (size_t)(((bh * F_ + r) * SPLIT) + sp) * 66;
        pp[2 + lane]      = a0;
        pp[2 + lane + 32] = a1;
        if (lane == 0) { pp[0] = M; pp[1] = red[r][1]; }
    }
}

__global__ void __launch_bounds__(64) attn_tred() {
    int t = blockIdx.x;                 // t = bh*F + i
    int i  = t % F_;
    int bh = t / F_;
    int h = bh % H_;
    int b = bh / H_;
    int d = threadIdx.x;

    float M = -1e30f;
    float ms[SPLIT], ss[SPLIT];
#pragma unroll
    for (int sp = 0; sp < SPLIT; sp++) {
        const float* pp = g_part + (size_t)(t * SPLIT + sp) * 66;
        ms[sp] = pp[0]; ss[sp] = pp[1];
        M = fmaxf(M, ms[sp]);
    }
    float S = 0.f, acc = 0.f;
#pragma unroll
    for (int sp = 0; sp < SPLIT; sp++) {
        float e = expf(ms[sp] - M);
        S += ss[sp] * e;
        acc += g_part[(size_t)(t * SPLIT + sp) * 66 + 2 + d] * e;
    }
    g_at[((size_t)(b * NTOK + i)) * C_ + h * D_ + d] = __float2half_rn(acc / S);
}

// ---------------- launch (stream fork/join, capture-safe) ----------------
extern "C" void kernel_launch(void* const* d_in, const int* in_sizes, int n_in,
                              void* d_out, int out_size) {
    const float* x     = (const float*)d_in[0];
    const float* ln_g  = (const float*)d_in[1];
    const float* ln_b  = (const float*)d_in[2];
    const float* qkvw  = (const float*)d_in[3];
    const float* projw = (const float*)d_in[4];
    const float* projb = (const float*)d_in[5];
    const float* fc1w  = (const float*)d_in[6];
    const float* fc1b  = (const float*)d_in[7];
    const float* fc2w  = (const float*)d_in[8];
    const float* fc2b  = (const float*)d_in[9];
    float* out = (float*)d_out;

    cudaFuncSetAttribute(gemm_mma<0>, cudaFuncAttributeMaxDynamicSharedMemorySize, SMEM_DYN);
    cudaFuncSetAttribute(gemm_mma<1>, cudaFuncAttributeMaxDynamicSharedMemorySize, SMEM_DYN);
    cudaFuncSetAttribute(gemm_mma<2>, cudaFuncAttributeMaxDynamicSharedMemorySize, SMEM_DYN);
    cudaFuncSetAttribute(gemm_mma<3>, cudaFuncAttributeMaxDynamicSharedMemorySize, SMEM_DYN);

    cudaStream_t s2;
    cudaStreamCreateWithFlags(&s2, cudaStreamNonBlocking);
    cudaEvent_t e0, e1, e2, e3, e4, e5;
    cudaEventCreateWithFlags(&e0, cudaEventDisableTiming);
    cudaEventCreateWithFlags(&e1, cudaEventDisableTiming);
    cudaEventCreateWithFlags(&e2, cudaEventDisableTiming);
    cudaEventCreateWithFlags(&e3, cudaEventDisableTiming);
    cudaEventCreateWithFlags(&e4, cudaEventDisableTiming);
    cudaEventCreateWithFlags(&e5, cudaEventDisableTiming);

    const int INIT_BLOCKS = (BN * C_ / 4 + 255) / 256;
    cudaStream_t m = 0;

    // ---- fork 1: ln1 (s2)  ||  cvt_all (main) ----
    cudaEventRecord(e0, m);
    cudaStreamWaitEvent(s2, e0, 0);
    ln_kernel<false><<<BN, 256, 0, s2>>>(x, ln_g, ln_b);
    cvt_all<<<(WTOT / 4 + 255) / 256, 256, 0, m>>>(qkvw, projw, fc1w, fc2w);
    cudaEventRecord(e1, s2);
    cudaStreamWaitEvent(m, e1, 0);

    // 2. g_qkv = g_h @ qkv_w^T
    gemm_mma<0><<<dim3(C3 / 128, (BN + 127) / 128), 256, SMEM_DYN, m>>>(nullptr, nullptr);

    // ---- fork 2: tpart->tred (s2)  ||  spatial + init_out1 (main) ----
    cudaEventRecord(e2, m);
    cudaStreamWaitEvent(s2, e2, 0);
    attn_tpart<<<B_ * H_ * SPLIT, 256, 0, s2>>>();
    attn_tred<<<B_ * H_ * F_, 64, 0, s2>>>();
    attn_spatial<<<B_ * H_ * (NSP / 8), 256, 0, m>>>();
    init_out1<<<INIT_BLOCKS, 256, 0, m>>>(projb);
    cudaEventRecord(e3, s2);
    cudaStreamWaitEvent(m, e3, 0);

    // 4. g_out += g_at @ proj_w^T  (split-K=2, atomic)
    gemm_mma<1><<<dim3(C_ / 128, (BN + 127) / 128, 2), 256, SMEM_DYN, m>>>(nullptr, nullptr);

    // ---- fork 3: init_out3 (s2)  ||  ln2 + fc1 (main) ----
    cudaEventRecord(e4, m);
    cudaStreamWaitEvent(s2, e4, 0);
    init_out3<<<INIT_BLOCKS, 256, 0, s2>>>(fc2b, out);
    ln_kernel<true><<<BN, 256, 0, m>>>(nullptr, ln_g, ln_b);
    gemm_mma<2><<<dim3(DFF / 128, (BN + 127) / 128), 256, SMEM_DYN, m>>>(fc1b, nullptr);
    cudaEventRecord(e5, s2);
    cudaStreamWaitEvent(m, e5, 0);

    // 7. out += g_m @ fc2_w^T  (split-K=2, atomic)
    gemm_mma<3><<<dim3(C_ / 128, (BN + 127) / 128, 2), 256, SMEM_DYN, m>>>(nullptr, out);
}

// round 15
// speedup vs baseline: 1.8852x; 1.0632x over previous
#include <cuda_runtime.h>
#include <cuda_fp16.h>
#include <math.h>
#include <stdint.h>

// ---------------- problem constants ----------------
static constexpr int B_   = 4;
static constexpr int NTOK = 1569;
static constexpr int C_   = 768;
static constexpr int H_   = 12;
static constexpr int D_   = 64;
static constexpr int F_   = 9;            // CLS + 8 temporal tokens
static constexpr int BN   = B_ * NTOK;    // 6276
static constexpr int C3   = 3 * C_;       // 2304
static constexpr int DFF  = 4 * C_;       // 3072
static constexpr int SPLIT = 12;          // temporal-attention key split
static constexpr int NSP  = NTOK - F_;    // 1560 spatial keys
static constexpr int KPB  = NSP / SPLIT;  // 130 keys per block
static constexpr int SROWS = 32;          // spatial rows per block
static constexpr int SCH  = (NSP + SROWS - 1) / SROWS;  // 49

// ---------------- scratch (device globals; no allocs) ----------------
__device__ __align__(16) float g_qkv[BN * C3];        // qkv projection (fp32)
__device__ __align__(16) float g_out[BN * C_];        // proj output ("new x", fp32)
__device__ __align__(16) __half g_h[BN * C_];         // LN out (fp16)
__device__ __align__(16) __half g_at[BN * C_];        // attn out (fp16)
__device__ __align__(16) __half g_m[BN * DFF];        // fc1 out (fp16)
__device__ __align__(16) __half g_wq[C3 * C_];
__device__ __align__(16) __half g_wp[C_ * C_];
__device__ __align__(16) __half g_w1[DFF * C_];
__device__ __align__(16) __half g_w2[C_ * DFF];
__device__ float g_part[B_ * H_ * F_ * SPLIT * 66];   // split-softmax partials

// ---------------- helpers ----------------
__device__ __forceinline__ uint32_t smem_u32(const void* p) {
    uint32_t a;
    asm("{ .reg .u64 t; cvta.to.shared.u64 t, %1; cvt.u32.u64 %0, t; }" : "=r"(a) : "l"(p));
    return a;
}
__device__ __forceinline__ void cp16(uint32_t dst, const void* src, int sz) {
    asm volatile("cp.async.cg.shared.global [%0], [%1], 16, %2;" :: "r"(dst), "l"(src), "r"(sz) : "memory");
}
__device__ __forceinline__ void cp_commit() { asm volatile("cp.async.commit_group;" ::: "memory"); }
template <int N>
__device__ __forceinline__ void cp_wait() { asm volatile("cp.async.wait_group %0;" :: "n"(N) : "memory"); }

__device__ __forceinline__ void ldm_x4(uint32_t* r, uint32_t addr) {
    asm volatile("ldmatrix.sync.aligned.m8n8.x4.shared.b16 {%0,%1,%2,%3}, [%4];"
                 : "=r"(r[0]), "=r"(r[1]), "=r"(r[2]), "=r"(r[3]) : "r"(addr));
}
__device__ __forceinline__ void mma_f16(float* d, const uint32_t* a, uint32_t b0, uint32_t b1) {
    asm volatile("mma.sync.aligned.m16n8k16.row.col.f32.f16.f16.f32 "
                 "{%0,%1,%2,%3}, {%4,%5,%6,%7}, {%8,%9}, {%0,%1,%2,%3};"
                 : "+f"(d[0]), "+f"(d[1]), "+f"(d[2]), "+f"(d[3])
                 : "r"(a[0]), "r"(a[1]), "r"(a[2]), "r"(a[3]), "r"(b0), "r"(b1));
}

// ---------------- fused, vectorized weight convert (fp32 -> fp16) ----------------
static constexpr int WSEG0 = C3 * C_;
static constexpr int WSEG1 = WSEG0 + C_ * C_;
static constexpr int WSEG2 = WSEG1 + DFF * C_;
static constexpr int WTOT  = WSEG2 + C_ * DFF;

__global__ void __launch_bounds__(256) cvt_all(const float* __restrict__ wq,
                                               const float* __restrict__ wp,
                                               const float* __restrict__ w1,
                                               const float* __restrict__ w2) {
    int i4 = (blockIdx.x * 256 + threadIdx.x) * 4;
    if (i4 >= WTOT) return;
    const float* src; __half* dst; int loc;
    if (i4 < WSEG0)      { src = wq; dst = g_wq; loc = i4; }
    else if (i4 < WSEG1) { src = wp; dst = g_wp; loc = i4 - WSEG0; }
    else if (i4 < WSEG2) { src = w1; dst = g_w1; loc = i4 - WSEG1; }
    else                 { src = w2; dst = g_w2; loc = i4 - WSEG2; }
    float4 v = *(const float4*)(src + loc);
    __half2* hp = (__half2*)(dst + loc);
    hp[0] = __halves2half2(__float2half_rn(v.x), __float2half_rn(v.y));
    hp[1] = __halves2half2(__float2half_rn(v.z), __float2half_rn(v.w));
}

// ---------------- output-init kernels (absorb bias / residual for split-K) ----------------
__global__ void __launch_bounds__(256) init_out1(const float* __restrict__ bias) {
    int idx = (blockIdx.x * 256 + threadIdx.x) * 4;
    if (idx < BN * C_) *(float4*)&g_out[idx] = *(const float4*)&bias[idx % C_];
}
__global__ void __launch_bounds__(256) init_out3(const float* __restrict__ bias,
                                                 float* __restrict__ out) {
    int idx = (blockIdx.x * 256 + threadIdx.x) * 4;
    if (idx < BN * C_) {
        float4 g = *(const float4*)&g_out[idx];
        float4 b = *(const float4*)&bias[idx % C_];
        *(float4*)&out[idx] = make_float4(g.x + b.x, g.y + b.y, g.z + b.z, g.w + b.w);
    }
}

// ---------------- LayerNorm -> fp16 into g_h ----------------
template <bool FROM_OUT>
__global__ void __launch_bounds__(256) ln_kernel(const float* __restrict__ ext_in,
                                                 const float* __restrict__ gam,
                                                 const float* __restrict__ bet) {
    const float* in = FROM_OUT ? g_out : ext_in;
    int row = blockIdx.x;
    const float* x = in + (size_t)row * C_;
    int tid = threadIdx.x;
    float v0 = x[tid], v1 = x[tid + 256], v2 = x[tid + 512];
    float s  = v0 + v1 + v2;
    float ss = v0 * v0 + v1 * v1 + v2 * v2;
#pragma unroll
    for (int off = 16; off; off >>= 1) {
        s  += __shfl_xor_sync(0xffffffffu, s, off);
        ss += __shfl_xor_sync(0xffffffffu, ss, off);
    }
    __shared__ float sm[8], sm2[8], stats[2];
    int warp = tid >> 5, lane = tid & 31;
    if (lane == 0) { sm[warp] = s; sm2[warp] = ss; }
    __syncthreads();
    if (tid == 0) {
        float S = 0.f, SS = 0.f;
#pragma unroll
        for (int w = 0; w < 8; w++) { S += sm[w]; SS += sm2[w]; }
        float mean = S * (1.0f / C_);
        float var  = SS * (1.0f / C_) - mean * mean;
        stats[0] = mean;
        stats[1] = rsqrtf(var + 1e-5f);
    }
    __syncthreads();
    float mean = stats[0], rstd = stats[1];
    size_t base = (size_t)row * C_;
#pragma unroll
    for (int t = 0; t < 3; t++) {
        int c = tid + t * 256;
        float v = t == 0 ? v0 : (t == 1 ? v1 : v2);
        float y = (v - mean) * rstd * gam[c] + bet[c];
        g_h[base + c] = __float2half_rn(y);
    }
}

// ---------------- HMMA GEMM: C[M,Nn] = A[M,K] @ W[Nn,K]^T (plain fp16 x fp16) ----------------
static constexpr int STAGE_BYTES = 32768;   // A 16KB | W 16KB, xor-swizzled
static constexpr int SMEM_DYN = 2 * STAGE_BYTES;   // 64 KB

template <int CFG>
__global__ void __launch_bounds__(256, 2)
gemm_mma(const float* __restrict__ bias, float* __restrict__ ext_out) {
    constexpr int Nn = (CFG == 0) ? C3 : (CFG == 2) ? DFF : C_;
    constexpr int K  = (CFG == 3) ? DFF : C_;
    constexpr bool SK = (CFG == 1 || CFG == 3);
    constexpr int NCH = (K / 64) / (SK ? 2 : 1);

    const __half* A = (CFG == 0 || CFG == 2) ? g_h : (CFG == 1) ? g_at : g_m;
    const __half* W = (CFG == 0) ? g_wq : (CFG == 1) ? g_wp : (CFG == 2) ? g_w1 : g_w2;

    extern __shared__ char smraw[];
    uint32_t sbu = smem_u32(smraw);

    int tid = threadIdx.x, lane = tid & 31, wid = tid >> 5;
    int n0 = blockIdx.x * 128, m0 = blockIdx.y * 128;
    int c0 = SK ? (int)blockIdx.z * NCH : 0;
    int wm0 = (wid & 3) * 32, wn0 = (wid >> 2) * 64;

    auto issue = [&](int c, int s) {
        int k0 = c * 64;
        uint32_t sb = sbu + (uint32_t)s * STAGE_BYTES;
#pragma unroll
        for (int it = 0; it < 4; it++) {
            int idx = tid + it * 256;          // 0..1023
            int row = idx >> 3, unit = idx & 7;
            uint32_t soff = (uint32_t)row * 128u + (uint32_t)((unit ^ (row & 7)) << 4);
            int grA = m0 + row;
            int szA = (grA < BN) ? 16 : 0;
            cp16(sb + soff, A + (size_t)grA * K + k0 + unit * 8, szA);
            cp16(sb + 16384 + soff, W + (size_t)(n0 + row) * K + k0 + unit * 8, 16);
        }
        cp_commit();
    };

    float d[2][8][4];
#pragma unroll
    for (int i = 0; i < 2; i++)
#pragma unroll
        for (int j = 0; j < 8; j++)
#pragma unroll
            for (int q = 0; q < 4; q++) d[i][j][q] = 0.f;

    issue(c0, 0);
    for (int cc = 0; cc < NCH; cc++) {
        if (cc + 1 < NCH) { issue(c0 + cc + 1, (cc + 1) & 1); cp_wait<1>(); }
        else              { cp_wait<0>(); }
        __syncthreads();
        uint32_t sb = sbu + (uint32_t)(cc & 1) * STAGE_BYTES;
#pragma unroll
        for (int kk = 0; kk < 4; kk++) {
            uint32_t a[2][4];
#pragma unroll
            for (int mt = 0; mt < 2; mt++) {
                int row = wm0 + mt * 16 + (lane & 15);
                int unit = kk * 2 + (lane >> 4);
                uint32_t off = (uint32_t)row * 128u + (uint32_t)((unit ^ (row & 7)) << 4);
                ldm_x4(a[mt], sb + off);
            }
#pragma unroll
            for (int ng = 0; ng < 4; ng++) {
                int row = wn0 + ng * 16 + (lane & 15);
                int unit = kk * 2 + (lane >> 4);
                uint32_t off = (uint32_t)row * 128u + (uint32_t)((unit ^ (row & 7)) << 4);
                uint32_t b4[4];
                ldm_x4(b4, sb + 16384 + off);
#pragma unroll
                for (int mt = 0; mt < 2; mt++)
#pragma unroll
                    for (int hf = 0; hf < 2; hf++) {
                        mma_f16(d[mt][ng * 2 + hf], a[mt], b4[hf], b4[hf + 2]);
                    }
            }
        }
        __syncthreads();
    }

    // epilogue
#pragma unroll
    for (int mt = 0; mt < 2; mt++) {
#pragma unroll
        for (int half = 0; half < 2; half++) {
            int grow = m0 + wm0 + mt * 16 + (lane >> 2) + half * 8;
            if (grow >= BN) continue;
#pragma unroll
            for (int nt = 0; nt < 8; nt++) {
                int gc = n0 + wn0 + nt * 8 + (lane & 3) * 2;
                float v0 = d[mt][nt][half * 2 + 0];
                float v1 = d[mt][nt][half * 2 + 1];
                size_t o = (size_t)grow * Nn + gc;
                if constexpr (CFG == 0) {
                    *(float2*)&g_qkv[o] = make_float2(v0, v1);
                } else if constexpr (CFG == 1) {
                    atomicAdd(&g_out[o], v0);
                    atomicAdd(&g_out[o + 1], v1);
                } else if constexpr (CFG == 2) {
                    v0 += bias[gc]; v1 += bias[gc + 1];
                    v0 = 0.5f * v0 * (1.0f + erff(v0 * 0.70710678f));
                    v1 = 0.5f * v1 * (1.0f + erff(v1 * 0.70710678f));
                    g_m[o]     = __float2half_rn(v0);
                    g_m[o + 1] = __float2half_rn(v1);
                } else {
                    atomicAdd(&ext_out[o], v0);
                    atomicAdd(&ext_out[o + 1], v1);
                }
            }
        }
    }
}

// ---------------- attention, spatial rows: 8-lanes-per-row (4 rows/warp) ----------------
__global__ void __launch_bounds__(256) attn_spatial() {
    const float* qkv = g_qkv;
    int bid   = blockIdx.x;
    int chunk = bid % SCH;
    int bh    = bid / SCH;
    int h     = bh % H_;
    int b     = bh / H_;

    __shared__ float ks[F_][D_], vs[F_][D_];
    int tid = threadIdx.x;
    for (int idx = tid; idx < F_ * D_; idx += 256) {
        int j = idx / D_, dd = idx % D_;
        const float* base = qkv + ((size_t)(b * NTOK + j)) * C3 + h * D_;
        ks[j][dd] = base[C_ + dd];
        vs[j][dd] = base[2 * C_ + dd];
    }
    __syncthreads();

    int warp = tid >> 5, lane = tid & 31;
    int sub = lane >> 3, d0 = lane & 7;
    int roff = chunk * SROWS + warp * 4 + sub;      // 0..1567
    bool ok = roff < NSP;
    int i = F_ + (ok ? roff : NSP - 1);             // clamp loads, guard stores
    const float* q = qkv + ((size_t)(b * NTOK + i)) * C3 + h * D_;

    float qreg[8];
#pragma unroll
    for (int k = 0; k < 8; k++) qreg[k] = q[d0 + 8 * k];

    float lg[F_];
#pragma unroll
    for (int j = 0; j < F_; j++) {
        float p = 0.f;
#pragma unroll
        for (int k = 0; k < 8; k++) p += qreg[k] * ks[j][d0 + 8 * k];
        p += __shfl_xor_sync(0xffffffffu, p, 1);
        p += __shfl_xor_sync(0xffffffffu, p, 2);
        p += __shfl_xor_sync(0xffffffffu, p, 4);
        lg[j] = p * 0.125f;
    }
    float m = lg[0];
#pragma unroll
    for (int j = 1; j < F_; j++) m = fmaxf(m, lg[j]);
    float wj[F_], s = 0.f;
#pragma unroll
    for (int j = 0; j < F_; j++) { wj[j] = expf(lg[j] - m); s += wj[j]; }
    float inv = 1.0f / s;

    float acc[8];
#pragma unroll
    for (int k = 0; k < 8; k++) acc[k] = 0.f;
#pragma unroll
    for (int j = 0; j < F_; j++)
#pragma unroll
        for (int k = 0; k < 8; k++) acc[k] += wj[j] * vs[j][d0 + 8 * k];

    if (ok) {
        size_t off0 = ((size_t)(b * NTOK + i)) * C_ + h * D_;
#pragma unroll
        for (int k = 0; k < 8; k++)
            g_at[off0 + d0 + 8 * k] = __float2half_rn(acc[k] * inv);
    }
}

// ---------------- temporal rows: smem-tiled, 9 warps, K-tile reused for V ----------------
__global__ void __launch_bounds__(288) attn_tpart() {
    const float* qkv = g_qkv;
    int bid = blockIdx.x;
    int sp = bid % SPLIT;
    int bh = bid / SPLIT;
    int h  = bh % H_;
    int b  = bh / H_;

    __shared__ float qsh[F_][D_];            // 2.3 KB
    __shared__ float kt[KPB + 1][D_ + 3];    // 131 x 67 fp32 = 35.1 KB (K, then reused for V)
    __shared__ float lgs[KPB + 1][F_];       // 4.7 KB
    __shared__ float red[F_][2];             // Mb, Sb

    int tid = threadIdx.x, w = tid >> 5, lane = tid & 31;
    int base = F_ + sp * KPB;
    int cnt = KPB + (sp == 0 ? 1 : 0);

    // stage Q and K tile
    for (int idx = tid; idx < F_ * D_; idx += 288)
        qsh[idx / D_][idx % D_] = qkv[((size_t)(b * NTOK + idx / D_)) * C3 + h * D_ + idx % D_];
    for (int idx = tid; idx < KPB * D_; idx += 288) {
        int j = idx / D_, d = idx % D_;
        kt[j][d] = qkv[((size_t)(b * NTOK + base + j)) * C3 + C_ + h * D_ + d];
    }
    if (sp == 0)
        for (int d = tid; d < D_; d += 288)
            kt[KPB][d] = qkv[((size_t)(b * NTOK + 0)) * C3 + C_ + h * D_ + d];
    __syncthreads();

    // pass 1: thread t = key t; all 9 logits, no shuffles
    if (tid < cnt) {
        float acc[F_];
#pragma unroll
        for (int i = 0; i < F_; i++) acc[i] = 0.f;
        for (int d = 0; d < D_; d++) {
            float kd = kt[tid][d];
#pragma unroll
            for (int i = 0; i < F_; i++) acc[i] += qsh[i][d] * kd;
        }
        bool cls = (tid == KPB);
#pragma unroll
        for (int i = 0; i < F_; i++)
            lgs[tid][i] = (cls && i > 0) ? -1e30f : acc[i] * 0.125f;
    }
    __syncthreads();   // pass 1 done: kt (K) dead, lgs live

    // stage V into kt (reuse)
    for (int idx = tid; idx < KPB * D_; idx += 288) {
        int j = idx / D_, d = idx % D_;
        kt[j][d] = qkv[((size_t)(b * NTOK + base + j)) * C3 + 2 * C_ + h * D_ + d];
    }
    if (sp == 0)
        for (int d = tid; d < D_; d += 288)
            kt[KPB][d] = qkv[((size_t)(b * NTOK + 0)) * C3 + 2 * C_ + h * D_ + d];

    // per-row block max / expsum (warp r = row r; 9 warps)
    if (w < F_) {
        int r = w;
        float mx = -1e30f, sm = 0.f;
        for (int t = lane; t < cnt; t += 32) {
            float lg = lgs[t][r];
            if (lg > mx) { sm *= expf(mx - lg); mx = lg; }
            sm += expf(lg - mx);
        }
#pragma unroll
        for (int off = 16; off; off >>= 1) {
            float mo = __shfl_xor_sync(0xffffffffu, mx, off);
            float so = __shfl_xor_sync(0xffffffffu, sm, off);
            float Mx = fmaxf(mx, mo);
            sm = sm * expf(mx - Mx) + so * expf(mo - Mx);
            mx = Mx;
        }
        if (lane == 0) { red[r][0] = mx; red[r][1] = sm; }
    }
    __syncthreads();   // V staged + reductions done

    // pass 2: warp r owns row r; V from smem (conflict-free)
    if (w < F_) {
        int r = w;
        float M = red[r][0];
        float a0 = 0.f, a1 = 0.f;
        for (int t = 0; t < cnt; t++) {
            float w8 = expf(lgs[t][r] - M);
            a0 += w8 * kt[t][lane];
            a1 += w8 * kt[t][lane + 32];
        }
        float* pp = g_part + (size_t)(((bh * F_ + r) * SPLIT) + sp) * 66;
        pp[2 + lane]      = a0;
        pp[2 + lane + 32] = a1;
        if (lane == 0) { pp[0] = M; pp[1] = red[r][1]; }
    }
}

__global__ void __launch_bounds__(64) attn_tred() {
    int t = blockIdx.x;                 // t = bh*F + i
    int i  = t % F_;
    int bh = t / F_;
    int h = bh % H_;
    int b = bh / H_;
    int d = threadIdx.x;

    float M = -1e30f;
    float ms[SPLIT], ss[SPLIT];
#pragma unroll
    for (int sp = 0; sp < SPLIT; sp++) {
        const float* pp = g_part + (size_t)(t * SPLIT + sp) * 66;
        ms[sp] = pp[0]; ss[sp] = pp[1];
        M = fmaxf(M, ms[sp]);
    }
    float S = 0.f, acc = 0.f;
#pragma unroll
    for (int sp = 0; sp < SPLIT; sp++) {
        float e = expf(ms[sp] - M);
        S += ss[sp] * e;
        acc += g_part[(size_t)(t * SPLIT + sp) * 66 + 2 + d] * e;
    }
    g_at[((size_t)(b * NTOK + i)) * C_ + h * D_ + d] = __float2half_rn(acc / S);
}

// ---------------- launch (stream fork/join, capture-safe) ----------------
extern "C" void kernel_launch(void* const* d_in, const int* in_sizes, int n_in,
                              void* d_out, int out_size) {
    const float* x     = (const float*)d_in[0];
    const float* ln_g  = (const float*)d_in[1];
    const float* ln_b  = (const float*)d_in[2];
    const float* qkvw  = (const float*)d_in[3];
    const float* projw = (const float*)d_in[4];
    const float* projb = (const float*)d_in[5];
    const float* fc1w  = (const float*)d_in[6];
    const float* fc1b  = (const float*)d_in[7];
    const float* fc2w  = (const float*)d_in[8];
    const float* fc2b  = (const float*)d_in[9];
    float* out = (float*)d_out;

    cudaFuncSetAttribute(gemm_mma<0>, cudaFuncAttributeMaxDynamicSharedMemorySize, SMEM_DYN);
    cudaFuncSetAttribute(gemm_mma<1>, cudaFuncAttributeMaxDynamicSharedMemorySize, SMEM_DYN);
    cudaFuncSetAttribute(gemm_mma<2>, cudaFuncAttributeMaxDynamicSharedMemorySize, SMEM_DYN);
    cudaFuncSetAttribute(gemm_mma<3>, cudaFuncAttributeMaxDynamicSharedMemorySize, SMEM_DYN);

    cudaStream_t s2;
    cudaStreamCreateWithFlags(&s2, cudaStreamNonBlocking);
    cudaEvent_t e0, e1, e2, e3, e4, e5;
    cudaEventCreateWithFlags(&e0, cudaEventDisableTiming);
    cudaEventCreateWithFlags(&e1, cudaEventDisableTiming);
    cudaEventCreateWithFlags(&e2, cudaEventDisableTiming);
    cudaEventCreateWithFlags(&e3, cudaEventDisableTiming);
    cudaEventCreateWithFlags(&e4, cudaEventDisableTiming);
    cudaEventCreateWithFlags(&e5, cudaEventDisableTiming);

    const int INIT_BLOCKS = (BN * C_ / 4 + 255) / 256;
    cudaStream_t m = 0;

    // ---- fork 1: ln1 (s2)  ||  cvt_all (main) ----
    cudaEventRecord(e0, m);
    cudaStreamWaitEvent(s2, e0, 0);
    ln_kernel<false><<<BN, 256, 0, s2>>>(x, ln_g, ln_b);
    cvt_all<<<(WTOT / 4 + 255) / 256, 256, 0, m>>>(qkvw, projw, fc1w, fc2w);
    cudaEventRecord(e1, s2);
    cudaStreamWaitEvent(m, e1, 0);

    // 2. g_qkv = g_h @ qkv_w^T
    gemm_mma<0><<<dim3(C3 / 128, (BN + 127) / 128), 256, SMEM_DYN, m>>>(nullptr, nullptr);

    // ---- fork 2: tpart->tred (s2)  ||  spatial + init_out1 (main) ----
    cudaEventRecord(e2, m);
    cudaStreamWaitEvent(s2, e2, 0);
    attn_tpart<<<B_ * H_ * SPLIT, 288, 0, s2>>>();
    attn_tred<<<B_ * H_ * F_, 64, 0, s2>>>();
    attn_spatial<<<B_ * H_ * SCH, 256, 0, m>>>();
    init_out1<<<INIT_BLOCKS, 256, 0, m>>>(projb);
    cudaEventRecord(e3, s2);
    cudaStreamWaitEvent(m, e3, 0);

    // 4. g_out += g_at @ proj_w^T  (split-K=2, atomic)
    gemm_mma<1><<<dim3(C_ / 128, (BN + 127) / 128, 2), 256, SMEM_DYN, m>>>(nullptr, nullptr);

    // ---- fork 3: init_out3 (s2)  ||  ln2 + fc1 (main) ----
    cudaEventRecord(e4, m);
    cudaStreamWaitEvent(s2, e4, 0);
    init_out3<<<INIT_BLOCKS, 256, 0, s2>>>(fc2b, out);
    ln_kernel<true><<<BN, 256, 0, m>>>(nullptr, ln_g, ln_b);
    gemm_mma<2><<<dim3(DFF / 128, (BN + 127) / 128), 256, SMEM_DYN, m>>>(fc1b, nullptr);
    cudaEventRecord(e5, s2);
    cudaStreamWaitEvent(m, e5, 0);

    // 7. out += g_m @ fc2_w^T  (split-K=2, atomic)
    gemm_mma<3><<<dim3(C_ / 128, (BN + 127) / 128, 2), 256, SMEM_DYN, m>>>(nullptr, out);
}